// round 1
// baseline (speedup 1.0000x reference)
#include <cuda_runtime.h>
#include <math.h>

#define N_NODES 20000
#define B_GR    128
#define FIN     768
#define RAWF    5000
#define HDIM    256

// ---------------- device scratch (no allocation allowed) ----------------
__device__ float g_h  [N_NODES * HDIM];   // GEMM output scratch
__device__ float g_xa [N_NODES * HDIM];   // layer ping
__device__ float g_xb [N_NODES * HDIM];   // layer pong
__device__ float g_dinv_g[N_NODES];
__device__ float g_dinv_r[N_NODES];
__device__ int   g_deg_g [N_NODES];
__device__ int   g_deg_r [N_NODES];
__device__ int   g_start [B_GR];
__device__ int   g_end   [B_GR];
__device__ float g_cat [B_GR * 2 * RAWF]; // [mean | root] concat, ld=10000
__device__ float g_h2  [B_GR * 512];      // branch-2 hidden (split-K target)
__device__ float g_nx  [B_GR * HDIM];     // branch-2 out (split-K target)
__device__ float g_f5  [B_GR * 5 * HDIM]; // concat feature [128,1280]

// ---------------- small utility kernels ----------------
__global__ void zero_f(float* p, int n) {
    for (int i = blockIdx.x * blockDim.x + threadIdx.x; i < n; i += gridDim.x * blockDim.x)
        p[i] = 0.f;
}
__global__ void zero_i(int* p, int n) {
    for (int i = blockIdx.x * blockDim.x + threadIdx.x; i < n; i += gridDim.x * blockDim.x)
        p[i] = 0;
}
__global__ void init_bounds(int* start, int* end) {
    int b = threadIdx.x;
    if (b < B_GR) { start[b] = N_NODES; end[b] = 0; }
}
__global__ void bounds_kernel(const int* __restrict__ batch, int* start, int* end, int n) {
    int i = blockIdx.x * blockDim.x + threadIdx.x;
    if (i >= n) return;
    int b = batch[i];
    atomicMin(&start[b], i);
    atomicMax(&end[b], i + 1);
}
__global__ void deg_kernel(const int* __restrict__ dst, int* deg, int E) {
    int e = blockIdx.x * blockDim.x + threadIdx.x;
    if (e < E) atomicAdd(&deg[dst[e]], 1);
}
__global__ void dinv_kernel(const int* __restrict__ deg, float* dinv, int n) {
    int i = blockIdx.x * blockDim.x + threadIdx.x;
    if (i < n) dinv[i] = rsqrtf((float)(deg[i] + 1)); // +1 self loop; always >=1
}

// ---------------- GEMM: C[M,N] (+)= A[M,K] @ B[K,N] ----------------
// 128x128 tile, BK=8, 8x8 per thread, 256 threads. Optional split-K via atomics.
template <bool ATOMIC>
__global__ void sgemm128(const float* __restrict__ A, const float* __restrict__ B,
                         float* __restrict__ C, int M, int N, int K, int ldc, int kChunk)
{
    __shared__ float As[8][128];
    __shared__ float Bs[8][128];
    const int tid = threadIdx.x;
    const int br = blockIdx.y * 128;
    const int bc = blockIdx.x * 128;
    int k0 = blockIdx.z * kChunk;
    int k1 = k0 + kChunk; if (k1 > K) k1 = K;

    const int tRow = (tid >> 4) << 3;  // 0..120
    const int tCol = (tid & 15) << 3;  // 0..120

    float acc[8][8];
#pragma unroll
    for (int i = 0; i < 8; i++)
#pragma unroll
        for (int j = 0; j < 8; j++) acc[i][j] = 0.f;

    const int aRow = tid >> 1;          // 0..127
    const int aCol = (tid & 1) << 2;    // 0 or 4
    const int bRow = tid >> 5;          // 0..7
    const int bCol = (tid & 31) << 2;   // 0..124
    const int gr = br + aRow;
    const int gc = bc + bCol;

    for (int k = k0; k < k1; k += 8) {
        float4 av = make_float4(0.f, 0.f, 0.f, 0.f);
        if (gr < M) av = *(const float4*)(A + (size_t)gr * K + k + aCol);
        As[aCol + 0][aRow] = av.x;
        As[aCol + 1][aRow] = av.y;
        As[aCol + 2][aRow] = av.z;
        As[aCol + 3][aRow] = av.w;
        float4 bv = make_float4(0.f, 0.f, 0.f, 0.f);
        if (gc < N) bv = *(const float4*)(B + (size_t)(k + bRow) * N + gc);
        *(float4*)(&Bs[bRow][bCol]) = bv;
        __syncthreads();
#pragma unroll
        for (int kk = 0; kk < 8; kk++) {
            float ra[8], rb[8];
#pragma unroll
            for (int i = 0; i < 8; i++) ra[i] = As[kk][tRow + i];
#pragma unroll
            for (int j = 0; j < 8; j++) rb[j] = Bs[kk][tCol + j];
#pragma unroll
            for (int i = 0; i < 8; i++)
#pragma unroll
                for (int j = 0; j < 8; j++)
                    acc[i][j] += ra[i] * rb[j];
        }
        __syncthreads();
    }
#pragma unroll
    for (int i = 0; i < 8; i++) {
        int r = br + tRow + i;
        if (r >= M) break;
#pragma unroll
        for (int j = 0; j < 8; j++) {
            int c = bc + tCol + j;
            if (c < N) {
                if (ATOMIC) atomicAdd(&C[(size_t)r * ldc + c], acc[i][j]);
                else        C[(size_t)r * ldc + c] = acc[i][j];
            }
        }
    }
}

// ---------------- GCN pieces ----------------
// out[i,f] = dinv[i]^2 * h[i,f]  (self-loop term initializes the accumulator)
__global__ void selfloop_init(const float* __restrict__ h, const float* __restrict__ dinv,
                              float* __restrict__ out, int n)
{
    int idx = blockIdx.x * blockDim.x + threadIdx.x;
    if (idx >= n) return;
    int row = idx >> 8; // HDIM = 256
    float dv = dinv[row];
    out[idx] = dv * dv * h[idx];
}

// warp per edge: out[dst] += dinv[s]*dinv[d] * h[src]  (lane-consecutive -> coalesced atomics)
__global__ void edge_agg(const float* __restrict__ h, const float* __restrict__ dinv,
                         const int* __restrict__ src, const int* __restrict__ dst,
                         float* __restrict__ out, int E)
{
    int gtid = blockIdx.x * blockDim.x + threadIdx.x;
    int e = gtid >> 5;
    int lane = gtid & 31;
    if (e >= E) return;
    int s = src[e], d = dst[e];
    float nv = dinv[s] * dinv[d];
    const float* hs = h + (size_t)s * HDIM;
    float* od = out + (size_t)d * HDIM;
#pragma unroll
    for (int f = lane; f < HDIM; f += 32)
        atomicAdd(od + f, nv * hs[f]);
}

__global__ void bias_relu(float* __restrict__ x, const float* __restrict__ b, int n)
{
    int idx = blockIdx.x * blockDim.x + threadIdx.x;
    if (idx >= n) return;
    float v = x[idx] + b[idx & (HDIM - 1)];
    x[idx] = v > 0.f ? v : 0.f;
}

// ---------------- pooling (batch is sorted -> contiguous segments) ----------------
__global__ void pool_max(const float* __restrict__ x,
                         const int* __restrict__ start, const int* __restrict__ end,
                         float* __restrict__ out, int ldo)
{
    int f = threadIdx.x;            // HDIM threads
    int b = blockIdx.y;
    int s = start[b], e = end[b];
    float m = -INFINITY;
    for (int r = s; r < e; r++) m = fmaxf(m, x[(size_t)r * HDIM + f]);
    out[(size_t)b * ldo + f] = m;
}

__global__ void pool_mean(const float* __restrict__ x, int F,
                          const int* __restrict__ start, const int* __restrict__ end,
                          float* __restrict__ out, int ldo)
{
    int f = blockIdx.x * blockDim.x + threadIdx.x;
    int b = blockIdx.y;
    if (f >= F) return;
    int s = start[b], e = end[b];
    float sum = 0.f;
    for (int r = s; r < e; r++) sum += x[(size_t)r * F + f];
    int cnt = e - s; if (cnt < 1) cnt = 1;
    out[(size_t)b * ldo + f] = sum / (float)cnt;
}

__global__ void gather_root(const float* __restrict__ x, const int* __restrict__ root,
                            float* __restrict__ out, int ldo)
{
    int f = blockIdx.x * blockDim.x + threadIdx.x;
    int b = blockIdx.y;
    if (f >= RAWF) return;
    out[(size_t)b * ldo + f] = x[(size_t)root[b] * RAWF + f];
}

__global__ void prelu_bias(const float* __restrict__ in, const float* __restrict__ bias,
                           const float* __restrict__ a_ptr, float* __restrict__ out,
                           int rows, int F, int ldo)
{
    int idx = blockIdx.x * blockDim.x + threadIdx.x;
    if (idx >= rows * F) return;
    int r = idx / F, f = idx - r * F;
    float a = *a_ptr;
    float v = in[idx] + bias[f];
    out[(size_t)r * ldo + f] = v >= 0.f ? v : a * v;
}

// ---------------- final head: [128,1280]@[1280,4] + log_softmax ----------------
__global__ void final_head(const float* __restrict__ feat, const float* __restrict__ W5,
                           const float* __restrict__ b5, float* __restrict__ out)
{
    int b = blockIdx.x;   // 128 blocks
    int t = threadIdx.x;  // 128 threads
    float a0 = 0.f, a1 = 0.f, a2 = 0.f, a3 = 0.f;
    const float* row = feat + (size_t)b * 1280;
    for (int k = t; k < 1280; k += 128) {
        float xv = row[k];
        const float* w = W5 + (size_t)k * 4;
        a0 += xv * w[0]; a1 += xv * w[1]; a2 += xv * w[2]; a3 += xv * w[3];
    }
    __shared__ float red[128][4];
    red[t][0] = a0; red[t][1] = a1; red[t][2] = a2; red[t][3] = a3;
    __syncthreads();
    for (int sft = 64; sft > 0; sft >>= 1) {
        if (t < sft) {
#pragma unroll
            for (int c = 0; c < 4; c++) red[t][c] += red[t + sft][c];
        }
        __syncthreads();
    }
    if (t == 0) {
        float v[4];
#pragma unroll
        for (int c = 0; c < 4; c++) v[c] = red[0][c] + b5[c];
        float m = fmaxf(fmaxf(v[0], v[1]), fmaxf(v[2], v[3]));
        float sum = 0.f;
#pragma unroll
        for (int c = 0; c < 4; c++) sum += expf(v[c] - m);
        float lse = m + logf(sum);
#pragma unroll
        for (int c = 0; c < 4; c++) out[(size_t)b * 4 + c] = v[c] - lse;
    }
}

// ---------------- host orchestration ----------------
static inline void gemm(const float* A, const float* B, float* C,
                        int M, int N, int K, int ldc, int splits)
{
    dim3 grid((N + 127) / 128, (M + 127) / 128, splits);
    if (splits > 1) {
        int chunk = ((K + splits - 1) / splits + 7) & ~7;
        sgemm128<true><<<grid, 256>>>(A, B, C, M, N, K, ldc, chunk);
    } else {
        sgemm128<false><<<grid, 256>>>(A, B, C, M, N, K, ldc, K);
    }
}

extern "C" void kernel_launch(void* const* d_in, const int* in_sizes, int n_in,
                              void* d_out, int out_size)
{
    const float* graph_x = (const float*)d_in[0];
    const float* data_x  = (const float*)d_in[2];
    const int*   ei      = (const int*)d_in[3];
    const int*   rei     = (const int*)d_in[4];
    const int*   batch   = (const int*)d_in[5];
    const int*   root    = (const int*)d_in[7];
    const float* W1  = (const float*)d_in[8];
    const float* b1  = (const float*)d_in[9];
    const float* Wc0 = (const float*)d_in[10];
    const float* bc0 = (const float*)d_in[11];
    const float* Wc1 = (const float*)d_in[12];
    const float* bc1 = (const float*)d_in[13];
    const float* Wc2 = (const float*)d_in[14];
    const float* bc2 = (const float*)d_in[15];
    const float* Wl1 = (const float*)d_in[16];
    const float* bl1 = (const float*)d_in[17];
    const float* Wl2 = (const float*)d_in[18];
    const float* bl2 = (const float*)d_in[19];
    const float* pa  = (const float*)d_in[20];
    const float* W5  = (const float*)d_in[21];
    const float* b5  = (const float*)d_in[22];
    float* out = (float*)d_out;

    const int E = in_sizes[3] / 2;

    float *h, *xa, *xb, *dg, *dr, *cat, *h2, *nx, *f5;
    int *degg, *degr, *st, *en;
    cudaGetSymbolAddress((void**)&h,    g_h);
    cudaGetSymbolAddress((void**)&xa,   g_xa);
    cudaGetSymbolAddress((void**)&xb,   g_xb);
    cudaGetSymbolAddress((void**)&dg,   g_dinv_g);
    cudaGetSymbolAddress((void**)&dr,   g_dinv_r);
    cudaGetSymbolAddress((void**)&degg, g_deg_g);
    cudaGetSymbolAddress((void**)&degr, g_deg_r);
    cudaGetSymbolAddress((void**)&st,   g_start);
    cudaGetSymbolAddress((void**)&en,   g_end);
    cudaGetSymbolAddress((void**)&cat,  g_cat);
    cudaGetSymbolAddress((void**)&h2,   g_h2);
    cudaGetSymbolAddress((void**)&nx,   g_nx);
    cudaGetSymbolAddress((void**)&f5,   g_f5);

    const int NT = 256;
    const int nNH = N_NODES * HDIM;

    // ---- degrees + dinv for both edge sets, segment bounds ----
    zero_i<<<128, NT>>>(degg, N_NODES);
    zero_i<<<128, NT>>>(degr, N_NODES);
    deg_kernel<<<(E + NT - 1) / NT, NT>>>(ei + E, degg, E);
    deg_kernel<<<(E + NT - 1) / NT, NT>>>(rei + E, degr, E);
    dinv_kernel<<<(N_NODES + NT - 1) / NT, NT>>>(degg, dg, N_NODES);
    dinv_kernel<<<(N_NODES + NT - 1) / NT, NT>>>(degr, dr, N_NODES);
    init_bounds<<<1, 128>>>(st, en);
    bounds_kernel<<<(N_NODES + NT - 1) / NT, NT>>>(batch, st, en, N_NODES);

    dim3 eagGrid((E * 32 + NT - 1) / NT);
    int nhBlocks = (nNH + NT - 1) / NT;

    // ---- branch 1: GCN(graph_x, W1) -> relu -> segment_max -> f5[:,1024:1280] ----
    gemm(graph_x, W1, h, N_NODES, HDIM, FIN, HDIM, 1);
    selfloop_init<<<nhBlocks, NT>>>(h, dg, xa, nNH);
    edge_agg<<<eagGrid, NT>>>(h, dg, ei, ei + E, xa, E);
    bias_relu<<<nhBlocks, NT>>>(xa, b1, nNH);
    pool_max<<<dim3(1, B_GR), HDIM>>>(xa, st, en, f5 + 1024, 1280);

    // ---- branch 3: 3 GCN layers on raw graph, mean pool each ----
    gemm(data_x, Wc0, h, N_NODES, HDIM, RAWF, HDIM, 1);
    selfloop_init<<<nhBlocks, NT>>>(h, dr, xa, nNH);
    edge_agg<<<eagGrid, NT>>>(h, dr, rei, rei + E, xa, E);
    bias_relu<<<nhBlocks, NT>>>(xa, bc0, nNH);
    pool_mean<<<dim3(1, B_GR), HDIM>>>(xa, HDIM, st, en, f5 + 0, 1280);

    gemm(xa, Wc1, h, N_NODES, HDIM, HDIM, HDIM, 1);
    selfloop_init<<<nhBlocks, NT>>>(h, dr, xb, nNH);
    edge_agg<<<eagGrid, NT>>>(h, dr, rei, rei + E, xb, E);
    bias_relu<<<nhBlocks, NT>>>(xb, bc1, nNH);
    pool_mean<<<dim3(1, B_GR), HDIM>>>(xb, HDIM, st, en, f5 + 256, 1280);

    gemm(xb, Wc2, h, N_NODES, HDIM, HDIM, HDIM, 1);
    selfloop_init<<<nhBlocks, NT>>>(h, dr, xa, nNH);
    edge_agg<<<eagGrid, NT>>>(h, dr, rei, rei + E, xa, E);
    bias_relu<<<nhBlocks, NT>>>(xa, bc2, nNH);
    pool_mean<<<dim3(1, B_GR), HDIM>>>(xa, HDIM, st, en, f5 + 512, 1280);

    // ---- branch 2: [segment_mean(data_x) | data_x[root]] -> MLP w/ PReLU ----
    pool_mean<<<dim3((RAWF + NT - 1) / NT, B_GR), NT>>>(data_x, RAWF, st, en, cat, 2 * RAWF);
    gather_root<<<dim3((RAWF + NT - 1) / NT, B_GR), NT>>>(data_x, root, cat + RAWF, 2 * RAWF);
    zero_f<<<64, NT>>>(h2, B_GR * 512);
    gemm(cat, Wl1, h2, B_GR, 512, 2 * RAWF, 512, 25);           // split-K
    prelu_bias<<<(B_GR * 512 + NT - 1) / NT, NT>>>(h2, bl1, pa, h2, B_GR, 512, 512);
    zero_f<<<64, NT>>>(nx, B_GR * HDIM);
    gemm(h2, Wl2, nx, B_GR, HDIM, 512, HDIM, 8);                // split-K
    prelu_bias<<<(B_GR * HDIM + NT - 1) / NT, NT>>>(nx, bl2, pa, f5 + 768, B_GR, HDIM, 1280);

    // ---- head: feat5 @ W5 + b5, log_softmax ----
    final_head<<<B_GR, 128>>>(f5, W5, b5, out);
}

// round 11
// speedup vs baseline: 1.9434x; 1.9434x over previous
#include <cuda_runtime.h>
#include <cuda_bf16.h>
#include <math.h>
#include <stdint.h>

#define N_NODES 20000
#define B_GR    128
#define FIN     768
#define RAWF    5000
#define HDIM    256
#define LDK     40   // padded SMEM k-stride (bf16 elems): 80B rows -> conflict-free ldmatrix

// ---------------- device scratch (no allocation allowed) ----------------
__device__ float g_h  [N_NODES * HDIM];   // GEMM output (pre-norm h)
__device__ float g_xa [N_NODES * HDIM];   // layer ping (aggregation accumulator)
__device__ float g_xb [N_NODES * HDIM];   // layer pong
__device__ float g_dinv_g[N_NODES];
__device__ float g_dinv_r[N_NODES];
__device__ int   g_deg_g [N_NODES];
__device__ int   g_deg_r [N_NODES];
__device__ int   g_start [B_GR];
__device__ int   g_end   [B_GR];
__device__ float g_cat [B_GR * 2 * RAWF]; // [mean | root] concat, ld=10000 (reused as nx scratch)
__device__ float g_h2  [B_GR * 512];      // branch-2 hidden (split-K target)
__device__ float g_f5  [B_GR * 5 * HDIM]; // concat feature [128,1280]
__device__ uint16_t g_whiT[256 * RAWF];   // W^T hi bf16  [256, K]
__device__ uint16_t g_wloT[256 * RAWF];   // W^T lo bf16  [256, K]

// ================= helpers =================
__device__ __forceinline__ uint32_t smem_u32(const void* p) {
    uint32_t a;
    asm("{ .reg .u64 t; cvta.to.shared.u64 t, %1; cvt.u32.u64 %0, t; }" : "=r"(a) : "l"(p));
    return a;
}
__device__ __forceinline__ void ldm_x4(uint32_t* r, uint32_t addr) {
    asm volatile("ldmatrix.sync.aligned.m8n8.x4.shared.b16 {%0,%1,%2,%3}, [%4];"
        : "=r"(r[0]), "=r"(r[1]), "=r"(r[2]), "=r"(r[3]) : "r"(addr));
}
__device__ __forceinline__ void mma16816(float* d, const uint32_t* a, const uint32_t* b) {
    asm volatile("mma.sync.aligned.m16n8k16.row.col.f32.bf16.bf16.f32 "
        "{%0,%1,%2,%3}, {%4,%5,%6,%7}, {%8,%9}, {%0,%1,%2,%3};"
        : "+f"(d[0]), "+f"(d[1]), "+f"(d[2]), "+f"(d[3])
        : "r"(a[0]), "r"(a[1]), "r"(a[2]), "r"(a[3]), "r"(b[0]), "r"(b[1]));
}

// ======== mma.sync GEMM: H[M,256] = A[M,K] @ W[K,256] via W^T hi/lo bf16 ========
// Fuses Xout[row,:] = dinv[row]^2 * H[row,:]
// grid.x = ceil(M/128); 512 threads; dynamic smem 61440B
__global__ void __launch_bounds__(512) gcn_gemm_mma(
    const float* __restrict__ A, const uint16_t* __restrict__ BhiT,
    const uint16_t* __restrict__ BloT, float* __restrict__ H,
    float* __restrict__ Xout, const float* __restrict__ dinv, int M, int K)
{
    extern __shared__ char smem[];
    uint16_t* sAhi = (uint16_t*)smem;              // [128][LDK]
    uint16_t* sAlo = sAhi + 128 * LDK;             // [128][LDK]
    uint16_t* sBhi = sAlo + 128 * LDK;             // [256][LDK]
    uint16_t* sBlo = sBhi + 256 * LDK;             // [256][LDK]

    const int tid  = threadIdx.x;
    const int wid  = tid >> 5;
    const int lane = tid & 31;
    const int wm   = wid >> 2;       // 0..3  -> m rows [wm*32, +32)
    const int wn   = wid & 3;        // 0..3  -> n cols [wn*64, +64)
    const int rowBase = blockIdx.x * 128;

    const uint32_t aHiB = smem_u32(sAhi);
    const uint32_t aLoB = smem_u32(sAlo);
    const uint32_t bHiB = smem_u32(sBhi);
    const uint32_t bLoB = smem_u32(sBlo);

    // ldmatrix lane offsets (element units)
    const int qa = lane >> 3, ia = lane & 7;
    const int aRowLane = ia + ((qa & 1) << 3);   // row within m16
    const int aKLane   = (qa >> 1) << 3;         // k offset within k16
    const int bRowLane = ia + ((qa >> 1) << 3);  // n within n16
    const int bKLane   = (qa & 1) << 3;

    float acc[2][8][4];
#pragma unroll
    for (int i = 0; i < 2; i++)
#pragma unroll
        for (int j = 0; j < 8; j++)
#pragma unroll
            for (int l = 0; l < 4; l++) acc[i][j][l] = 0.f;

    const int nCh = (K + 31) / 32;

    for (int c = 0; c < nCh; c++) {
        const int kg = c * 32;
        // ---- stage A: 128 rows x 32 fp32 -> hi/lo bf16 (8 floats / thread) ----
        {
            int row = tid >> 2, kb = (tid & 3) << 3;
            int grow = rowBase + row, gk = kg + kb;
            float v[8];
#pragma unroll
            for (int j = 0; j < 8; j++) v[j] = 0.f;
            if (grow < M) {
                if (gk + 8 <= K) {
                    float4 v0 = *(const float4*)(A + (size_t)grow * K + gk);
                    float4 v1 = *(const float4*)(A + (size_t)grow * K + gk + 4);
                    v[0]=v0.x; v[1]=v0.y; v[2]=v0.z; v[3]=v0.w;
                    v[4]=v1.x; v[5]=v1.y; v[6]=v1.z; v[7]=v1.w;
                } else {
#pragma unroll
                    for (int j = 0; j < 8; j++)
                        if (gk + j < K) v[j] = A[(size_t)grow * K + gk + j];
                }
            }
            uint16_t hi[8], lo[8];
#pragma unroll
            for (int j = 0; j < 8; j++) {
                __nv_bfloat16 hb = __float2bfloat16_rn(v[j]);
                float res = v[j] - __bfloat162float(hb);
                __nv_bfloat16 lb = __float2bfloat16_rn(res);
                hi[j] = __bfloat16_as_ushort(hb);
                lo[j] = __bfloat16_as_ushort(lb);
            }
            *(uint4*)(&sAhi[row * LDK + kb]) = *(uint4*)hi;
            *(uint4*)(&sAlo[row * LDK + kb]) = *(uint4*)lo;
        }
        // ---- stage B: 256 n-rows x 32 k bf16 (hi & lo), 2 slots / thread ----
#pragma unroll
        for (int sl = 0; sl < 2; sl++) {
            int s = tid + sl * 512;        // 0..1023
            int n = s >> 2, kb = (s & 3) << 3;
            int gk = kg + kb;
            uint4 hv, lv;
            if (gk + 8 <= K) {
                hv = *(const uint4*)(BhiT + (size_t)n * K + gk);
                lv = *(const uint4*)(BloT + (size_t)n * K + gk);
            } else {
                uint16_t ht[8], lt[8];
#pragma unroll
                for (int j = 0; j < 8; j++) {
                    ht[j] = (gk + j < K) ? BhiT[(size_t)n * K + gk + j] : 0;
                    lt[j] = (gk + j < K) ? BloT[(size_t)n * K + gk + j] : 0;
                }
                hv = *(uint4*)ht; lv = *(uint4*)lt;
            }
            *(uint4*)(&sBhi[n * LDK + kb]) = hv;
            *(uint4*)(&sBlo[n * LDK + kb]) = lv;
        }
        __syncthreads();

        // ---- compute: 2 ksteps x (2 m-frags) x (4 n-groups of n16) x 3 passes ----
#pragma unroll
        for (int ks = 0; ks < 2; ks++) {
            uint32_t ahi[2][4], alo[2][4];
#pragma unroll
            for (int mf = 0; mf < 2; mf++) {
                uint32_t off = (uint32_t)(((wm * 32 + mf * 16 + aRowLane) * LDK
                                          + ks * 16 + aKLane) * 2);
                ldm_x4(ahi[mf], aHiB + off);
                ldm_x4(alo[mf], aLoB + off);
            }
#pragma unroll
            for (int ng = 0; ng < 4; ng++) {
                uint32_t offB = (uint32_t)(((wn * 64 + ng * 16 + bRowLane) * LDK
                                           + ks * 16 + bKLane) * 2);
                uint32_t bhi[4], blo[4];
                ldm_x4(bhi, bHiB + offB);
                ldm_x4(blo, bLoB + offB);
#pragma unroll
                for (int mf = 0; mf < 2; mf++) {
                    float* d0 = acc[mf][2 * ng];
                    float* d1 = acc[mf][2 * ng + 1];
                    mma16816(d0, ahi[mf], bhi + 0);
                    mma16816(d0, ahi[mf], blo + 0);
                    mma16816(d0, alo[mf], bhi + 0);
                    mma16816(d1, ahi[mf], bhi + 2);
                    mma16816(d1, ahi[mf], blo + 2);
                    mma16816(d1, alo[mf], bhi + 2);
                }
            }
        }
        __syncthreads();
    }

    // ---- epilogue: H + fused self-loop-scaled Xout ----
#pragma unroll
    for (int mf = 0; mf < 2; mf++) {
        int rb = rowBase + wm * 32 + mf * 16 + (lane >> 2);
#pragma unroll
        for (int rr = 0; rr < 2; rr++) {
            int row = rb + rr * 8;
            if (row >= M) continue;
            float dv = dinv[row];
            float dv2 = dv * dv;
            float* Hp = H    + (size_t)row * 256 + wn * 64 + (lane & 3) * 2;
            float* Xp = Xout + (size_t)row * 256 + wn * 64 + (lane & 3) * 2;
#pragma unroll
            for (int ng = 0; ng < 8; ng++) {
                float v0 = acc[mf][ng][rr * 2 + 0];
                float v1 = acc[mf][ng][rr * 2 + 1];
                float2 hvv = make_float2(v0, v1);
                float2 xvv = make_float2(dv2 * v0, dv2 * v1);
                *(float2*)(Hp + ng * 8) = hvv;
                *(float2*)(Xp + ng * 8) = xvv;
            }
        }
    }
}
#define MMA_SMEM (( (128 + 128 + 256 + 256) * LDK ) * 2)

// ---- W[K,256] -> W^T hi/lo bf16 [256,K] ----
__global__ void wsplit(const float* __restrict__ W, int K,
                       uint16_t* __restrict__ hiT, uint16_t* __restrict__ loT)
{
    int idx = blockIdx.x * blockDim.x + threadIdx.x;
    if (idx >= K * 256) return;
    int k = idx >> 8, n = idx & 255;
    float v = W[(size_t)k * 256 + n];
    __nv_bfloat16 hb = __float2bfloat16_rn(v);
    float lo = v - __bfloat162float(hb);
    __nv_bfloat16 lb = __float2bfloat16_rn(lo);
    hiT[(size_t)n * K + k] = __bfloat16_as_ushort(hb);
    loT[(size_t)n * K + k] = __bfloat16_as_ushort(lb);
}

// ---------------- small utility kernels ----------------
__global__ void zero_f(float* p, int n) {
    for (int i = blockIdx.x * blockDim.x + threadIdx.x; i < n; i += gridDim.x * blockDim.x)
        p[i] = 0.f;
}
__global__ void zero_i(int* p, int n) {
    for (int i = blockIdx.x * blockDim.x + threadIdx.x; i < n; i += gridDim.x * blockDim.x)
        p[i] = 0;
}
__global__ void init_bounds(int* start, int* end) {
    int b = threadIdx.x;
    if (b < B_GR) { start[b] = N_NODES; end[b] = 0; }
}
__global__ void bounds_kernel(const int* __restrict__ batch, int* start, int* end, int n) {
    int i = blockIdx.x * blockDim.x + threadIdx.x;
    if (i >= n) return;
    int b = batch[i];
    atomicMin(&start[b], i);
    atomicMax(&end[b], i + 1);
}
__global__ void deg_kernel(const int* __restrict__ dst, int* deg, int E) {
    int e = blockIdx.x * blockDim.x + threadIdx.x;
    if (e < E) atomicAdd(&deg[dst[e]], 1);
}
__global__ void dinv_kernel(const int* __restrict__ deg, float* dinv, int n) {
    int i = blockIdx.x * blockDim.x + threadIdx.x;
    if (i < n) dinv[i] = rsqrtf((float)(deg[i] + 1));
}

// warp per edge, float4 + vector reduction: out[dst] += dinv[s]*dinv[d] * h[src]
__global__ void edge_agg(const float4* __restrict__ h4, const float* __restrict__ dinv,
                         const int* __restrict__ src, const int* __restrict__ dst,
                         float* __restrict__ out, int E)
{
    int gtid = blockIdx.x * blockDim.x + threadIdx.x;
    int e = gtid >> 5;
    int lane = gtid & 31;
    if (e >= E) return;
    int s = src[e], d = dst[e];
    float nv = dinv[s] * dinv[d];
    const float4* hs = h4 + (size_t)s * 64;
    float* od = out + (size_t)d * 256;
#pragma unroll
    for (int f = lane; f < 64; f += 32) {
        float4 v = hs[f];
        asm volatile("red.global.add.v4.f32 [%0], {%1, %2, %3, %4};"
                     :: "l"(od + 4 * f), "f"(nv * v.x), "f"(nv * v.y),
                        "f"(nv * v.z), "f"(nv * v.w) : "memory");
    }
}

__global__ void bias_relu(float* __restrict__ x, const float* __restrict__ b, int n)
{
    int idx = blockIdx.x * blockDim.x + threadIdx.x;
    if (idx >= n) return;
    float v = x[idx] + b[idx & (HDIM - 1)];
    x[idx] = v > 0.f ? v : 0.f;
}

// ---------------- pooling (batch sorted -> contiguous segments) ----------------
__global__ void pool_max(const float* __restrict__ x,
                         const int* __restrict__ start, const int* __restrict__ end,
                         float* __restrict__ out, int ldo)
{
    int f = threadIdx.x;
    int b = blockIdx.y;
    int s = start[b], e = end[b];
    float m = -INFINITY;
    for (int r = s; r < e; r++) m = fmaxf(m, x[(size_t)r * HDIM + f]);
    out[(size_t)b * ldo + f] = m;
}

__global__ void pool_mean(const float* __restrict__ x, int F,
                          const int* __restrict__ start, const int* __restrict__ end,
                          float* __restrict__ out, int ldo)
{
    int f = blockIdx.x * blockDim.x + threadIdx.x;
    int b = blockIdx.y;
    if (f >= F) return;
    int s = start[b], e = end[b];
    float sum = 0.f;
    for (int r = s; r < e; r++) sum += x[(size_t)r * F + f];
    int cnt = e - s; if (cnt < 1) cnt = 1;
    out[(size_t)b * ldo + f] = sum / (float)cnt;
}

__global__ void gather_root(const float* __restrict__ x, const int* __restrict__ root,
                            float* __restrict__ out, int ldo)
{
    int f = blockIdx.x * blockDim.x + threadIdx.x;
    int b = blockIdx.y;
    if (f >= RAWF) return;
    out[(size_t)b * ldo + f] = x[(size_t)root[b] * RAWF + f];
}

__global__ void prelu_bias(const float* __restrict__ in, const float* __restrict__ bias,
                           const float* __restrict__ a_ptr, float* __restrict__ out,
                           int rows, int F, int ldo)
{
    int idx = blockIdx.x * blockDim.x + threadIdx.x;
    if (idx >= rows * F) return;
    int r = idx / F, f = idx - r * F;
    float a = *a_ptr;
    float v = in[idx] + bias[f];
    out[(size_t)r * ldo + f] = v >= 0.f ? v : a * v;
}

// ---------------- FFMA GEMM (branch-2 only): C[M,N] (+)= A@B ----------------
template <bool ATOMIC>
__global__ void sgemm128(const float* __restrict__ A, const float* __restrict__ B,
                         float* __restrict__ C, int M, int N, int K, int ldc, int kChunk)
{
    __shared__ float As[8][128];
    __shared__ float Bs[8][128];
    const int tid = threadIdx.x;
    const int br = blockIdx.y * 128;
    const int bc = blockIdx.x * 128;
    int k0 = blockIdx.z * kChunk;
    int k1 = k0 + kChunk; if (k1 > K) k1 = K;

    const int tRow = (tid >> 4) << 3;
    const int tCol = (tid & 15) << 3;

    float acc[8][8];
#pragma unroll
    for (int i = 0; i < 8; i++)
#pragma unroll
        for (int j = 0; j < 8; j++) acc[i][j] = 0.f;

    const int aRow = tid >> 1;
    const int aCol = (tid & 1) << 2;
    const int bRow = tid >> 5;
    const int bCol = (tid & 31) << 2;
    const int gr = br + aRow;
    const int gc = bc + bCol;

    for (int k = k0; k < k1; k += 8) {
        float4 av = make_float4(0.f, 0.f, 0.f, 0.f);
        if (gr < M) av = *(const float4*)(A + (size_t)gr * K + k + aCol);
        As[aCol + 0][aRow] = av.x;
        As[aCol + 1][aRow] = av.y;
        As[aCol + 2][aRow] = av.z;
        As[aCol + 3][aRow] = av.w;
        float4 bv = make_float4(0.f, 0.f, 0.f, 0.f);
        if (gc < N) bv = *(const float4*)(B + (size_t)(k + bRow) * N + gc);
        *(float4*)(&Bs[bRow][bCol]) = bv;
        __syncthreads();
#pragma unroll
        for (int kk = 0; kk < 8; kk++) {
            float ra[8], rb[8];
#pragma unroll
            for (int i = 0; i < 8; i++) ra[i] = As[kk][tRow + i];
#pragma unroll
            for (int j = 0; j < 8; j++) rb[j] = Bs[kk][tCol + j];
#pragma unroll
            for (int i = 0; i < 8; i++)
#pragma unroll
                for (int j = 0; j < 8; j++)
                    acc[i][j] += ra[i] * rb[j];
        }
        __syncthreads();
    }
#pragma unroll
    for (int i = 0; i < 8; i++) {
        int r = br + tRow + i;
        if (r >= M) break;
#pragma unroll
        for (int j = 0; j < 8; j++) {
            int c = bc + tCol + j;
            if (c < N) {
                if (ATOMIC) atomicAdd(&C[(size_t)r * ldc + c], acc[i][j]);
                else        C[(size_t)r * ldc + c] = acc[i][j];
            }
        }
    }
}

// ---------------- final head: [128,1280]@[1280,4] + log_softmax ----------------
__global__ void final_head(const float* __restrict__ feat, const float* __restrict__ W5,
                           const float* __restrict__ b5, float* __restrict__ out)
{
    int b = blockIdx.x;
    int t = threadIdx.x;
    float a0 = 0.f, a1 = 0.f, a2 = 0.f, a3 = 0.f;
    const float* row = feat + (size_t)b * 1280;
    for (int k = t; k < 1280; k += 128) {
        float xv = row[k];
        const float* w = W5 + (size_t)k * 4;
        a0 += xv * w[0]; a1 += xv * w[1]; a2 += xv * w[2]; a3 += xv * w[3];
    }
    __shared__ float red[128][4];
    red[t][0] = a0; red[t][1] = a1; red[t][2] = a2; red[t][3] = a3;
    __syncthreads();
    for (int sft = 64; sft > 0; sft >>= 1) {
        if (t < sft) {
#pragma unroll
            for (int c = 0; c < 4; c++) red[t][c] += red[t + sft][c];
        }
        __syncthreads();
    }
    if (t == 0) {
        float v[4];
#pragma unroll
        for (int c = 0; c < 4; c++) v[c] = red[0][c] + b5[c];
        float m = fmaxf(fmaxf(v[0], v[1]), fmaxf(v[2], v[3]));
        float sum = 0.f;
#pragma unroll
        for (int c = 0; c < 4; c++) sum += expf(v[c] - m);
        float lse = m + logf(sum);
#pragma unroll
        for (int c = 0; c < 4; c++) out[(size_t)b * 4 + c] = v[c] - lse;
    }
}

// ---------------- host orchestration ----------------
static inline void gemm_ffma(const float* A, const float* B, float* C,
                             int M, int N, int K, int ldc, int splits)
{
    dim3 grid((N + 127) / 128, (M + 127) / 128, splits);
    if (splits > 1) {
        int chunk = ((K + splits - 1) / splits + 7) & ~7;
        sgemm128<true><<<grid, 256>>>(A, B, C, M, N, K, ldc, chunk);
    } else {
        sgemm128<false><<<grid, 256>>>(A, B, C, M, N, K, ldc, K);
    }
}

extern "C" void kernel_launch(void* const* d_in, const int* in_sizes, int n_in,
                              void* d_out, int out_size)
{
    const float* graph_x = (const float*)d_in[0];
    const float* data_x  = (const float*)d_in[2];
    const int*   ei      = (const int*)d_in[3];
    const int*   rei     = (const int*)d_in[4];
    const int*   batch   = (const int*)d_in[5];
    const int*   root    = (const int*)d_in[7];
    const float* W1  = (const float*)d_in[8];
    const float* b1  = (const float*)d_in[9];
    const float* Wc0 = (const float*)d_in[10];
    const float* bc0 = (const float*)d_in[11];
    const float* Wc1 = (const float*)d_in[12];
    const float* bc1 = (const float*)d_in[13];
    const float* Wc2 = (const float*)d_in[14];
    const float* bc2 = (const float*)d_in[15];
    const float* Wl1 = (const float*)d_in[16];
    const float* bl1 = (const float*)d_in[17];
    const float* Wl2 = (const float*)d_in[18];
    const float* bl2 = (const float*)d_in[19];
    const float* pa  = (const float*)d_in[20];
    const float* W5  = (const float*)d_in[21];
    const float* b5  = (const float*)d_in[22];
    float* out = (float*)d_out;

    const int E = in_sizes[3] / 2;

    float *h, *xa, *xb, *dg, *dr, *cat, *h2, *f5;
    int *degg, *degr, *st, *en;
    uint16_t *whiT, *wloT;
    cudaGetSymbolAddress((void**)&h,    g_h);
    cudaGetSymbolAddress((void**)&xa,   g_xa);
    cudaGetSymbolAddress((void**)&xb,   g_xb);
    cudaGetSymbolAddress((void**)&dg,   g_dinv_g);
    cudaGetSymbolAddress((void**)&dr,   g_dinv_r);
    cudaGetSymbolAddress((void**)&degg, g_deg_g);
    cudaGetSymbolAddress((void**)&degr, g_deg_r);
    cudaGetSymbolAddress((void**)&st,   g_start);
    cudaGetSymbolAddress((void**)&en,   g_end);
    cudaGetSymbolAddress((void**)&cat,  g_cat);
    cudaGetSymbolAddress((void**)&h2,   g_h2);
    cudaGetSymbolAddress((void**)&f5,   g_f5);
    cudaGetSymbolAddress((void**)&whiT, g_whiT);
    cudaGetSymbolAddress((void**)&wloT, g_wloT);

    cudaFuncSetAttribute(gcn_gemm_mma, cudaFuncAttributeMaxDynamicSharedMemorySize, MMA_SMEM);

    const int NT = 256;
    const int nNH = N_NODES * HDIM;
    const int gemmGrid = (N_NODES + 127) / 128;

    // ---- degrees + dinv for both edge sets, segment bounds ----
    zero_i<<<128, NT>>>(degg, N_NODES);
    zero_i<<<128, NT>>>(degr, N_NODES);
    deg_kernel<<<(E + NT - 1) / NT, NT>>>(ei + E, degg, E);
    deg_kernel<<<(E + NT - 1) / NT, NT>>>(rei + E, degr, E);
    dinv_kernel<<<(N_NODES + NT - 1) / NT, NT>>>(degg, dg, N_NODES);
    dinv_kernel<<<(N_NODES + NT - 1) / NT, NT>>>(degr, dr, N_NODES);
    init_bounds<<<1, 128>>>(st, en);
    bounds_kernel<<<(N_NODES + NT - 1) / NT, NT>>>(batch, st, en, N_NODES);

    dim3 eagGrid((E * 32 + NT - 1) / NT);
    int nhBlocks = (nNH + NT - 1) / NT;

    // ---- branch 1: GCN(graph_x, W1) -> relu -> segment_max -> f5[:,1024:1280] ----
    wsplit<<<(FIN * 256 + NT - 1) / NT, NT>>>(W1, FIN, whiT, wloT);
    gcn_gemm_mma<<<gemmGrid, 512, MMA_SMEM>>>(graph_x, whiT, wloT, h, xa, dg, N_NODES, FIN);
    edge_agg<<<eagGrid, NT>>>((const float4*)h, dg, ei, ei + E, xa, E);
    bias_relu<<<nhBlocks, NT>>>(xa, b1, nNH);
    pool_max<<<dim3(1, B_GR), HDIM>>>(xa, st, en, f5 + 1024, 1280);

    // ---- branch 3: 3 GCN layers on raw graph, mean pool each ----
    wsplit<<<(RAWF * 256 + NT - 1) / NT, NT>>>(Wc0, RAWF, whiT, wloT);
    gcn_gemm_mma<<<gemmGrid, 512, MMA_SMEM>>>(data_x, whiT, wloT, h, xa, dr, N_NODES, RAWF);
    edge_agg<<<eagGrid, NT>>>((const float4*)h, dr, rei, rei + E, xa, E);
    bias_relu<<<nhBlocks, NT>>>(xa, bc0, nNH);
    pool_mean<<<dim3(1, B_GR), HDIM>>>(xa, HDIM, st, en, f5 + 0, 1280);

    wsplit<<<(HDIM * 256 + NT - 1) / NT, NT>>>(Wc1, HDIM, whiT, wloT);
    gcn_gemm_mma<<<gemmGrid, 512, MMA_SMEM>>>(xa, whiT, wloT, h, xb, dr, N_NODES, HDIM);
    edge_agg<<<eagGrid, NT>>>((const float4*)h, dr, rei, rei + E, xb, E);
    bias_relu<<<nhBlocks, NT>>>(xb, bc1, nNH);
    pool_mean<<<dim3(1, B_GR), HDIM>>>(xb, HDIM, st, en, f5 + 256, 1280);

    wsplit<<<(HDIM * 256 + NT - 1) / NT, NT>>>(Wc2, HDIM, whiT, wloT);
    gcn_gemm_mma<<<gemmGrid, 512, MMA_SMEM>>>(xb, whiT, wloT, h, xa, dr, N_NODES, HDIM);
    edge_agg<<<eagGrid, NT>>>((const float4*)h, dr, rei, rei + E, xa, E);
    bias_relu<<<nhBlocks, NT>>>(xa, bc2, nNH);
    pool_mean<<<dim3(1, B_GR), HDIM>>>(xa, HDIM, st, en, f5 + 512, 1280);

    // ---- branch 2: [segment_mean(data_x) | data_x[root]] -> MLP w/ PReLU ----
    pool_mean<<<dim3((RAWF + NT - 1) / NT, B_GR), NT>>>(data_x, RAWF, st, en, cat, 2 * RAWF);
    gather_root<<<dim3((RAWF + NT - 1) / NT, B_GR), NT>>>(data_x, root, cat + RAWF, 2 * RAWF);
    zero_f<<<64, NT>>>(h2, B_GR * 512);
    gemm_ffma(cat, Wl1, h2, B_GR, 512, 2 * RAWF, 512, 25);
    prelu_bias<<<(B_GR * 512 + NT - 1) / NT, NT>>>(h2, bl1, pa, h2, B_GR, 512, 512);
    {
        float* nx = cat;  // cat fully consumed by the Wl1 GEMM above; reuse as scratch
        zero_f<<<64, NT>>>(nx, B_GR * HDIM);
        gemm_ffma(h2, Wl2, nx, B_GR, HDIM, 512, HDIM, 8);
        prelu_bias<<<(B_GR * HDIM + NT - 1) / NT, NT>>>(nx, bl2, pa, f5 + 768, B_GR, HDIM, 1280);
    }

    // ---- head: feat5 @ W5 + b5, log_softmax ----
    final_head<<<B_GR, 128>>>(f5, W5, b5, out);
}

// round 12
// speedup vs baseline: 3.7965x; 1.9536x over previous
#include <cuda_runtime.h>
#include <cuda_fp16.h>
#include <math.h>
#include <stdint.h>

#define N_NODES 20000
#define B_GR    128
#define FIN     768
#define RAWF    5000
#define HDIM    256
#define LDK     40     // padded SMEM k-stride (fp16 elems): 80B rows -> conflict-free ldmatrix
#define BM      144    // rows per CTA: ceil(20000/144)=139 <= 148 SMs -> single wave
#define NTG     384    // 12 warps: 3m x 4n

// ---------------- device scratch ----------------
__device__ float g_h  [N_NODES * HDIM];
__device__ float g_xa [N_NODES * HDIM];
__device__ float g_xb [N_NODES * HDIM];
__device__ float g_dinv_g[N_NODES];
__device__ float g_dinv_r[N_NODES];
__device__ int   g_deg_g [N_NODES];
__device__ int   g_deg_r [N_NODES];
__device__ int   g_start [B_GR];
__device__ int   g_end   [B_GR];
__device__ float g_cat [B_GR * 2 * RAWF];
__device__ float g_h2  [B_GR * 512];
__device__ float g_f5  [B_GR * 5 * HDIM];
__device__ uint16_t g_wT[256 * RAWF];     // W^T fp16 [256, K]

// ================= helpers =================
__device__ __forceinline__ uint32_t smem_u32(const void* p) {
    uint32_t a;
    asm("{ .reg .u64 t; cvta.to.shared.u64 t, %1; cvt.u32.u64 %0, t; }" : "=r"(a) : "l"(p));
    return a;
}
__device__ __forceinline__ void ldm_x4(uint32_t* r, uint32_t addr) {
    asm volatile("ldmatrix.sync.aligned.m8n8.x4.shared.b16 {%0,%1,%2,%3}, [%4];"
        : "=r"(r[0]), "=r"(r[1]), "=r"(r[2]), "=r"(r[3]) : "r"(addr));
}
__device__ __forceinline__ void mma16816(float* d, const uint32_t* a, const uint32_t* b) {
    asm volatile("mma.sync.aligned.m16n8k16.row.col.f32.f16.f16.f32 "
        "{%0,%1,%2,%3}, {%4,%5,%6,%7}, {%8,%9}, {%0,%1,%2,%3};"
        : "+f"(d[0]), "+f"(d[1]), "+f"(d[2]), "+f"(d[3])
        : "r"(a[0]), "r"(a[1]), "r"(a[2]), "r"(a[3]), "r"(b[0]), "r"(b[1]));
}
template<int N>
__device__ __forceinline__ void cp_wait() {
    asm volatile("cp.async.wait_group %0;" :: "n"(N) : "memory");
}
__device__ __forceinline__ void cp_commit() {
    asm volatile("cp.async.commit_group;" ::: "memory");
}
__device__ __forceinline__ void cp_async16(uint32_t dst, const void* src, int srcsize) {
    asm volatile("cp.async.cg.shared.global [%0], [%1], 16, %2;"
        :: "r"(dst), "l"(src), "r"(srcsize) : "memory");
}

// SMEM layout (byte offsets, per-buffer):
//  A_HI(p) = p*23040 ; A_LO(p) = p*23040 + 11520   (144*LDK fp16 each = 11520 B)
//  B_BUF(p) = 46080 + p*20480                       (256*LDK fp16 = 20480 B)
#define MMA_SMEM (46080 + 2 * 20480)

// ======== pipelined mma.sync GEMM: H[M,256] = T(A)[M,K] @ W[K,256] ========
// T(A) = relu(A + abias) if abias != null, else A.    (fused prev-layer bias+relu)
// Fuses Xout[row,:] = dinv[row]^2 * H[row,:]          (GCN self-loop init)
// A split hi/lo fp16 (exact), W rounded to fp16 -> 2 MMA passes.
__global__ void __launch_bounds__(NTG) gcn_gemm_mma(
    const float* __restrict__ A, const uint16_t* __restrict__ BT,
    float* __restrict__ H, float* __restrict__ Xout,
    const float* __restrict__ dinv, const float* __restrict__ abias, int M, int K)
{
    extern __shared__ char smem[];
    const int tid  = threadIdx.x;
    const int wid  = tid >> 5;
    const int lane = tid & 31;
    const int wm   = wid >> 2;       // 0..2 -> rows [wm*48, +48)
    const int wn   = wid & 3;        // 0..3 -> cols [wn*64, +64)
    const int rowBase = blockIdx.x * BM;
    const uint32_t sb = smem_u32(smem);

    const int qa = lane >> 3, ia = lane & 7;
    const int aRowLane = ia + ((qa & 1) << 3);
    const int aKLane   = (qa >> 1) << 3;
    const int bRowLane = ia + ((qa >> 1) << 3);
    const int bKLane   = (qa & 1) << 3;

    float acc[3][8][4];
#pragma unroll
    for (int i = 0; i < 3; i++)
#pragma unroll
        for (int j = 0; j < 8; j++)
#pragma unroll
            for (int l = 0; l < 4; l++) acc[i][j][l] = 0.f;

    const int nCh = (K + 31) / 32;
    float va[2][8];

    // ---- lambdas as macros via inline code ----
    // LDG A chunk kg -> va regs. 576 slots (144 rows x 4 segs of 8 floats)
#define LDG_A(kg_) do { \
    _Pragma("unroll") \
    for (int sl = 0; sl < 2; sl++) { \
        int slot = tid + sl * NTG; \
        if (slot >= 576) break; \
        int row = slot >> 2, seg = slot & 3; \
        int grow = rowBase + row, gk = (kg_) + seg * 8; \
        _Pragma("unroll") \
        for (int j = 0; j < 8; j++) va[sl][j] = 0.f; \
        if (grow < M && gk + 8 <= K) { \
            float4 v0 = *(const float4*)(A + (size_t)grow * K + gk); \
            float4 v1 = *(const float4*)(A + (size_t)grow * K + gk + 4); \
            va[sl][0]=v0.x; va[sl][1]=v0.y; va[sl][2]=v0.z; va[sl][3]=v0.w; \
            va[sl][4]=v1.x; va[sl][5]=v1.y; va[sl][6]=v1.z; va[sl][7]=v1.w; \
        } \
    } } while (0)

    // transform + convert + STS into buffer p
#define CVT_STS_A(kg_, p_) do { \
    _Pragma("unroll") \
    for (int sl = 0; sl < 2; sl++) { \
        int slot = tid + sl * NTG; \
        if (slot >= 576) break; \
        int row = slot >> 2, seg = slot & 3; \
        int grow = rowBase + row, gk = (kg_) + seg * 8; \
        float v[8]; \
        _Pragma("unroll") \
        for (int j = 0; j < 8; j++) v[j] = va[sl][j]; \
        if (abias && grow < M && gk + 8 <= K) { \
            _Pragma("unroll") \
            for (int j = 0; j < 8; j++) v[j] = fmaxf(v[j] + abias[gk + j], 0.f); \
        } \
        uint16_t hi[8], lo[8]; \
        _Pragma("unroll") \
        for (int j = 0; j < 8; j++) { \
            __half hh = __float2half_rn(v[j]); \
            float  rs = v[j] - __half2float(hh); \
            hi[j] = __half_as_ushort(hh); \
            lo[j] = __half_as_ushort(__float2half_rn(rs)); \
        } \
        int off = (row * LDK + seg * 8) * 2; \
        *(uint4*)(smem + (p_) * 23040 + off)         = *(uint4*)hi; \
        *(uint4*)(smem + (p_) * 23040 + 11520 + off) = *(uint4*)lo; \
    } } while (0)

    // cp.async B chunk kg -> buffer p (1024 x 16B)
#define CPA_B(kg_, p_) do { \
    _Pragma("unroll") \
    for (int s = tid; s < 1024; s += NTG) { \
        int n = s >> 2, seg = s & 3; \
        int gk = (kg_) + seg * 8; \
        uint32_t dst = sb + 46080 + (p_) * 20480 + (uint32_t)(n * LDK + seg * 8) * 2; \
        cp_async16(dst, BT + (size_t)n * K + gk, (gk + 8 <= K) ? 16 : 0); \
    } } while (0)

    // ---- prolog ----
    LDG_A(0);
    CPA_B(0, 0);
    cp_commit();
    CVT_STS_A(0, 0);

    for (int c = 0; c < nCh; c++) {
        const int p = c & 1, q = p ^ 1;
        const int kgN = (c + 1) * 32;
        __syncthreads();                       // all warps done with buf q; A(c) STS visible
        if (c + 1 < nCh) {
            LDG_A(kgN);
            CPA_B(kgN, q);
            cp_commit();
            cp_wait<1>();                      // B(c) arrived, B(c+1) in flight
        } else {
            cp_wait<0>();
        }
        __syncthreads();                       // B(c) visible to all warps

        // ---- compute chunk c from buffer p ----
        const uint32_t aHiB = sb + p * 23040;
        const uint32_t aLoB = aHiB + 11520;
        const uint32_t bB   = sb + 46080 + p * 20480;
#pragma unroll
        for (int ks = 0; ks < 2; ks++) {
            uint32_t ahi[3][4], alo[3][4];
#pragma unroll
            for (int mf = 0; mf < 3; mf++) {
                uint32_t off = (uint32_t)(((wm * 48 + mf * 16 + aRowLane) * LDK
                                          + ks * 16 + aKLane) * 2);
                ldm_x4(ahi[mf], aHiB + off);
                ldm_x4(alo[mf], aLoB + off);
            }
#pragma unroll
            for (int ng = 0; ng < 4; ng++) {
                uint32_t offB = (uint32_t)(((wn * 64 + ng * 16 + bRowLane) * LDK
                                           + ks * 16 + bKLane) * 2);
                uint32_t b[4];
                ldm_x4(b, bB + offB);
#pragma unroll
                for (int mf = 0; mf < 3; mf++) {
                    float* d0 = acc[mf][2 * ng];
                    float* d1 = acc[mf][2 * ng + 1];
                    mma16816(d0, ahi[mf], b + 0);
                    mma16816(d0, alo[mf], b + 0);
                    mma16816(d1, ahi[mf], b + 2);
                    mma16816(d1, alo[mf], b + 2);
                }
            }
        }
        if (c + 1 < nCh) CVT_STS_A(kgN, q);
    }

    // ---- epilogue: H + fused self-loop-scaled Xout ----
#pragma unroll
    for (int mf = 0; mf < 3; mf++) {
        int rb = rowBase + wm * 48 + mf * 16 + (lane >> 2);
#pragma unroll
        for (int rr = 0; rr < 2; rr++) {
            int row = rb + rr * 8;
            if (row >= M) continue;
            float dv = dinv[row];
            float dv2 = dv * dv;
            float* Hp = H    + (size_t)row * 256 + wn * 64 + (lane & 3) * 2;
            float* Xp = Xout + (size_t)row * 256 + wn * 64 + (lane & 3) * 2;
#pragma unroll
            for (int g = 0; g < 8; g++) {
                float v0 = acc[mf][g][rr * 2 + 0];
                float v1 = acc[mf][g][rr * 2 + 1];
                *(float2*)(Hp + g * 8) = make_float2(v0, v1);
                *(float2*)(Xp + g * 8) = make_float2(dv2 * v0, dv2 * v1);
            }
        }
    }
#undef LDG_A
#undef CVT_STS_A
#undef CPA_B
}

// ---- W[K,256] -> W^T fp16 [256,K] ----
__global__ void wconv(const float* __restrict__ W, int K, uint16_t* __restrict__ wT)
{
    int idx = blockIdx.x * blockDim.x + threadIdx.x;
    if (idx >= K * 256) return;
    int k = idx >> 8, n = idx & 255;
    wT[(size_t)n * K + k] = __half_as_ushort(__float2half_rn(W[(size_t)k * 256 + n]));
}

// ---------------- small utility kernels ----------------
__global__ void zero_f(float* p, int n) {
    for (int i = blockIdx.x * blockDim.x + threadIdx.x; i < n; i += gridDim.x * blockDim.x)
        p[i] = 0.f;
}
__global__ void zero_i(int* p, int n) {
    for (int i = blockIdx.x * blockDim.x + threadIdx.x; i < n; i += gridDim.x * blockDim.x)
        p[i] = 0;
}
__global__ void init_bounds(int* start, int* end) {
    int b = threadIdx.x;
    if (b < B_GR) { start[b] = N_NODES; end[b] = 0; }
}
__global__ void bounds_kernel(const int* __restrict__ batch, int* start, int* end, int n) {
    int i = blockIdx.x * blockDim.x + threadIdx.x;
    if (i >= n) return;
    int b = batch[i];
    atomicMin(&start[b], i);
    atomicMax(&end[b], i + 1);
}
__global__ void deg_kernel(const int* __restrict__ dst, int* deg, int E) {
    int e = blockIdx.x * blockDim.x + threadIdx.x;
    if (e < E) atomicAdd(&deg[dst[e]], 1);
}
__global__ void dinv_kernel(const int* __restrict__ deg, float* dinv, int n) {
    int i = blockIdx.x * blockDim.x + threadIdx.x;
    if (i < n) dinv[i] = rsqrtf((float)(deg[i] + 1));
}

// warp per edge: out[dst] += dinv[s]*dinv[d] * h[src]
__global__ void edge_agg(const float4* __restrict__ h4, const float* __restrict__ dinv,
                         const int* __restrict__ src, const int* __restrict__ dst,
                         float* __restrict__ out, int E)
{
    int gtid = blockIdx.x * blockDim.x + threadIdx.x;
    int e = gtid >> 5;
    int lane = gtid & 31;
    if (e >= E) return;
    int s = src[e], d = dst[e];
    float nv = dinv[s] * dinv[d];
    const float4* hs = h4 + (size_t)s * 64;
    float* od = out + (size_t)d * 256;
#pragma unroll
    for (int f = lane; f < 64; f += 32) {
        float4 v = hs[f];
        asm volatile("red.global.add.v4.f32 [%0], {%1, %2, %3, %4};"
                     :: "l"(od + 4 * f), "f"(nv * v.x), "f"(nv * v.y),
                        "f"(nv * v.z), "f"(nv * v.w) : "memory");
    }
}

// ---------------- fused bias+relu pooling (batch sorted -> contiguous segments) ----------------
__global__ void pool_max_br(const float* __restrict__ x, const float* __restrict__ bias,
                            const int* __restrict__ start, const int* __restrict__ end,
                            float* __restrict__ out, int ldo)
{
    int f = threadIdx.x;            // HDIM threads
    int b = blockIdx.x;
    int s = start[b], e = end[b];
    float bv = bias[f];
    float m = -INFINITY;
    for (int r = s; r < e; r++) m = fmaxf(m, fmaxf(x[(size_t)r * HDIM + f] + bv, 0.f));
    out[(size_t)b * ldo + f] = m;
}

__global__ void pool_mean_br(const float* __restrict__ x, const float* __restrict__ bias,
                             const int* __restrict__ start, const int* __restrict__ end,
                             float* __restrict__ out, int ldo)
{
    int f = threadIdx.x;            // HDIM threads
    int b = blockIdx.x;
    int s = start[b], e = end[b];
    float bv = bias[f];
    float sum = 0.f;
    for (int r = s; r < e; r++) sum += fmaxf(x[(size_t)r * HDIM + f] + bv, 0.f);
    int cnt = e - s; if (cnt < 1) cnt = 1;
    out[(size_t)b * ldo + f] = sum / (float)cnt;
}

__global__ void pool_mean_wide(const float* __restrict__ x, int F,
                               const int* __restrict__ start, const int* __restrict__ end,
                               float* __restrict__ out, int ldo)
{
    int f = blockIdx.x * blockDim.x + threadIdx.x;
    int b = blockIdx.y;
    if (f >= F) return;
    int s = start[b], e = end[b];
    float sum = 0.f;
    for (int r = s; r < e; r++) sum += x[(size_t)r * F + f];
    int cnt = e - s; if (cnt < 1) cnt = 1;
    out[(size_t)b * ldo + f] = sum / (float)cnt;
}

__global__ void gather_root(const float* __restrict__ x, const int* __restrict__ root,
                            float* __restrict__ out, int ldo)
{
    int f = blockIdx.x * blockDim.x + threadIdx.x;
    int b = blockIdx.y;
    if (f >= RAWF) return;
    out[(size_t)b * ldo + f] = x[(size_t)root[b] * RAWF + f];
}

__global__ void prelu_bias(const float* __restrict__ in, const float* __restrict__ bias,
                           const float* __restrict__ a_ptr, float* __restrict__ out,
                           int rows, int F, int ldo)
{
    int idx = blockIdx.x * blockDim.x + threadIdx.x;
    if (idx >= rows * F) return;
    int r = idx / F, f = idx - r * F;
    float a = *a_ptr;
    float v = in[idx] + bias[f];
    out[(size_t)r * ldo + f] = v >= 0.f ? v : a * v;
}

// ---------------- FFMA GEMM (branch-2 only) ----------------
template <bool ATOMIC>
__global__ void sgemm128(const float* __restrict__ A, const float* __restrict__ B,
                         float* __restrict__ C, int M, int N, int K, int ldc, int kChunk)
{
    __shared__ float As[8][128];
    __shared__ float Bs[8][128];
    const int tid = threadIdx.x;
    const int br = blockIdx.y * 128;
    const int bc = blockIdx.x * 128;
    int k0 = blockIdx.z * kChunk;
    int k1 = k0 + kChunk; if (k1 > K) k1 = K;

    const int tRow = (tid >> 4) << 3;
    const int tCol = (tid & 15) << 3;

    float acc[8][8];
#pragma unroll
    for (int i = 0; i < 8; i++)
#pragma unroll
        for (int j = 0; j < 8; j++) acc[i][j] = 0.f;

    const int aRow = tid >> 1;
    const int aCol = (tid & 1) << 2;
    const int bRow = tid >> 5;
    const int bCol = (tid & 31) << 2;
    const int gr = br + aRow;
    const int gc = bc + bCol;

    for (int k = k0; k < k1; k += 8) {
        float4 av = make_float4(0.f, 0.f, 0.f, 0.f);
        if (gr < M) av = *(const float4*)(A + (size_t)gr * K + k + aCol);
        As[aCol + 0][aRow] = av.x;
        As[aCol + 1][aRow] = av.y;
        As[aCol + 2][aRow] = av.z;
        As[aCol + 3][aRow] = av.w;
        float4 bv = make_float4(0.f, 0.f, 0.f, 0.f);
        if (gc < N) bv = *(const float4*)(B + (size_t)(k + bRow) * N + gc);
        *(float4*)(&Bs[bRow][bCol]) = bv;
        __syncthreads();
#pragma unroll
        for (int kk = 0; kk < 8; kk++) {
            float ra[8], rb[8];
#pragma unroll
            for (int i = 0; i < 8; i++) ra[i] = As[kk][tRow + i];
#pragma unroll
            for (int j = 0; j < 8; j++) rb[j] = Bs[kk][tCol + j];
#pragma unroll
            for (int i = 0; i < 8; i++)
#pragma unroll
                for (int j = 0; j < 8; j++)
                    acc[i][j] += ra[i] * rb[j];
        }
        __syncthreads();
    }
#pragma unroll
    for (int i = 0; i < 8; i++) {
        int r = br + tRow + i;
        if (r >= M) break;
#pragma unroll
        for (int j = 0; j < 8; j++) {
            int c = bc + tCol + j;
            if (c < N) {
                if (ATOMIC) atomicAdd(&C[(size_t)r * ldc + c], acc[i][j]);
                else        C[(size_t)r * ldc + c] = acc[i][j];
            }
        }
    }
}

// ---------------- final head ----------------
__global__ void final_head(const float* __restrict__ feat, const float* __restrict__ W5,
                           const float* __restrict__ b5, float* __restrict__ out)
{
    int b = blockIdx.x;
    int t = threadIdx.x;
    float a0 = 0.f, a1 = 0.f, a2 = 0.f, a3 = 0.f;
    const float* row = feat + (size_t)b * 1280;
    for (int k = t; k < 1280; k += 128) {
        float xv = row[k];
        const float* w = W5 + (size_t)k * 4;
        a0 += xv * w[0]; a1 += xv * w[1]; a2 += xv * w[2]; a3 += xv * w[3];
    }
    __shared__ float red[128][4];
    red[t][0] = a0; red[t][1] = a1; red[t][2] = a2; red[t][3] = a3;
    __syncthreads();
    for (int sft = 64; sft > 0; sft >>= 1) {
        if (t < sft) {
#pragma unroll
            for (int c = 0; c < 4; c++) red[t][c] += red[t + sft][c];
        }
        __syncthreads();
    }
    if (t == 0) {
        float v[4];
#pragma unroll
        for (int c = 0; c < 4; c++) v[c] = red[0][c] + b5[c];
        float m = fmaxf(fmaxf(v[0], v[1]), fmaxf(v[2], v[3]));
        float sum = 0.f;
#pragma unroll
        for (int c = 0; c < 4; c++) sum += expf(v[c] - m);
        float lse = m + logf(sum);
#pragma unroll
        for (int c = 0; c < 4; c++) out[(size_t)b * 4 + c] = v[c] - lse;
    }
}

// ---------------- host orchestration ----------------
static inline void gemm_ffma(const float* A, const float* B, float* C,
                             int M, int N, int K, int ldc, int splits)
{
    dim3 grid((N + 127) / 128, (M + 127) / 128, splits);
    if (splits > 1) {
        int chunk = ((K + splits - 1) / splits + 7) & ~7;
        sgemm128<true><<<grid, 256>>>(A, B, C, M, N, K, ldc, chunk);
    } else {
        sgemm128<false><<<grid, 256>>>(A, B, C, M, N, K, ldc, K);
    }
}

extern "C" void kernel_launch(void* const* d_in, const int* in_sizes, int n_in,
                              void* d_out, int out_size)
{
    const float* graph_x = (const float*)d_in[0];
    const float* data_x  = (const float*)d_in[2];
    const int*   ei      = (const int*)d_in[3];
    const int*   rei     = (const int*)d_in[4];
    const int*   batch   = (const int*)d_in[5];
    const int*   root    = (const int*)d_in[7];
    const float* W1  = (const float*)d_in[8];
    const float* b1  = (const float*)d_in[9];
    const float* Wc0 = (const float*)d_in[10];
    const float* bc0 = (const float*)d_in[11];
    const float* Wc1 = (const float*)d_in[12];
    const float* bc1 = (const float*)d_in[13];
    const float* Wc2 = (const float*)d_in[14];
    const float* bc2 = (const float*)d_in[15];
    const float* Wl1 = (const float*)d_in[16];
    const float* bl1 = (const float*)d_in[17];
    const float* Wl2 = (const float*)d_in[18];
    const float* bl2 = (const float*)d_in[19];
    const float* pa  = (const float*)d_in[20];
    const float* W5  = (const float*)d_in[21];
    const float* b5  = (const float*)d_in[22];
    float* out = (float*)d_out;

    const int E = in_sizes[3] / 2;

    float *h, *xa, *xb, *dg, *dr, *cat, *h2, *f5;
    int *degg, *degr, *st, *en;
    uint16_t *wT;
    cudaGetSymbolAddress((void**)&h,    g_h);
    cudaGetSymbolAddress((void**)&xa,   g_xa);
    cudaGetSymbolAddress((void**)&xb,   g_xb);
    cudaGetSymbolAddress((void**)&dg,   g_dinv_g);
    cudaGetSymbolAddress((void**)&dr,   g_dinv_r);
    cudaGetSymbolAddress((void**)&degg, g_deg_g);
    cudaGetSymbolAddress((void**)&degr, g_deg_r);
    cudaGetSymbolAddress((void**)&st,   g_start);
    cudaGetSymbolAddress((void**)&en,   g_end);
    cudaGetSymbolAddress((void**)&cat,  g_cat);
    cudaGetSymbolAddress((void**)&h2,   g_h2);
    cudaGetSymbolAddress((void**)&f5,   g_f5);
    cudaGetSymbolAddress((void**)&wT,   g_wT);

    cudaFuncSetAttribute(gcn_gemm_mma, cudaFuncAttributeMaxDynamicSharedMemorySize, MMA_SMEM);

    const int NT = 256;
    const int gemmGrid = (N_NODES + BM - 1) / BM;   // 139 <= 148 -> single wave

    // ---- degrees + dinv + segment bounds ----
    zero_i<<<128, NT>>>(degg, N_NODES);
    zero_i<<<128, NT>>>(degr, N_NODES);
    deg_kernel<<<(E + NT - 1) / NT, NT>>>(ei + E, degg, E);
    deg_kernel<<<(E + NT - 1) / NT, NT>>>(rei + E, degr, E);
    dinv_kernel<<<(N_NODES + NT - 1) / NT, NT>>>(degg, dg, N_NODES);
    dinv_kernel<<<(N_NODES + NT - 1) / NT, NT>>>(degr, dr, N_NODES);
    init_bounds<<<1, 128>>>(st, en);
    bounds_kernel<<<(N_NODES + NT - 1) / NT, NT>>>(batch, st, en, N_NODES);

    dim3 eagGrid((E * 32 + NT - 1) / NT);

    // ---- branch 1: GCN(graph_x, W1) -> (bias+relu fused in pool) -> max pool ----
    wconv<<<(FIN * 256 + NT - 1) / NT, NT>>>(W1, FIN, wT);
    gcn_gemm_mma<<<gemmGrid, NTG, MMA_SMEM>>>(graph_x, wT, h, xa, dg, nullptr, N_NODES, FIN);
    edge_agg<<<eagGrid, NT>>>((const float4*)h, dg, ei, ei + E, xa, E);
    pool_max_br<<<B_GR, HDIM>>>(xa, b1, st, en, f5 + 1024, 1280);

    // ---- branch 3: 3 GCN layers; bias+relu fused into next GEMM's A-transform + pool ----
    wconv<<<(RAWF * 256 + NT - 1) / NT, NT>>>(Wc0, RAWF, wT);
    gcn_gemm_mma<<<gemmGrid, NTG, MMA_SMEM>>>(data_x, wT, h, xa, dr, nullptr, N_NODES, RAWF);
    edge_agg<<<eagGrid, NT>>>((const float4*)h, dr, rei, rei + E, xa, E);
    pool_mean_br<<<B_GR, HDIM>>>(xa, bc0, st, en, f5 + 0, 1280);

    wconv<<<(HDIM * 256 + NT - 1) / NT, NT>>>(Wc1, HDIM, wT);
    gcn_gemm_mma<<<gemmGrid, NTG, MMA_SMEM>>>(xa, wT, h, xb, dr, bc0, N_NODES, HDIM);
    edge_agg<<<eagGrid, NT>>>((const float4*)h, dr, rei, rei + E, xb, E);
    pool_mean_br<<<B_GR, HDIM>>>(xb, bc1, st, en, f5 + 256, 1280);

    wconv<<<(HDIM * 256 + NT - 1) / NT, NT>>>(Wc2, HDIM, wT);
    gcn_gemm_mma<<<gemmGrid, NTG, MMA_SMEM>>>(xb, wT, h, xa, dr, bc1, N_NODES, HDIM);
    edge_agg<<<eagGrid, NT>>>((const float4*)h, dr, rei, rei + E, xa, E);
    pool_mean_br<<<B_GR, HDIM>>>(xa, bc2, st, en, f5 + 512, 1280);

    // ---- branch 2: [segment_mean(data_x) | data_x[root]] -> MLP w/ PReLU ----
    pool_mean_wide<<<dim3((RAWF + NT - 1) / NT, B_GR), NT>>>(data_x, RAWF, st, en, cat, 2 * RAWF);
    gather_root<<<dim3((RAWF + NT - 1) / NT, B_GR), NT>>>(data_x, root, cat + RAWF, 2 * RAWF);
    zero_f<<<64, NT>>>(h2, B_GR * 512);
    gemm_ffma(cat, Wl1, h2, B_GR, 512, 2 * RAWF, 512, 25);
    prelu_bias<<<(B_GR * 512 + NT - 1) / NT, NT>>>(h2, bl1, pa, h2, B_GR, 512, 512);
    {
        float* nx = cat;  // cat fully consumed above; reuse as scratch
        zero_f<<<64, NT>>>(nx, B_GR * HDIM);
        gemm_ffma(h2, Wl2, nx, B_GR, HDIM, 512, HDIM, 8);
        prelu_bias<<<(B_GR * HDIM + NT - 1) / NT, NT>>>(nx, bl2, pa, f5 + 768, B_GR, HDIM, 1280);
    }

    // ---- head ----
    final_head<<<B_GR, 128>>>(f5, W5, b5, out);
}

// round 13
// speedup vs baseline: 4.2207x; 1.1117x over previous
#include <cuda_runtime.h>
#include <cuda_fp16.h>
#include <math.h>
#include <stdint.h>

#define N_NODES 20000
#define B_GR    128
#define FIN     768
#define RAWF    5000
#define HDIM    256
#define LDK     40     // padded SMEM k-stride (fp16 elems)
#define BM      144    // rows per CTA: ceil(20000/144)=139 <= 148 SMs -> single wave
#define NTG     384    // 12 warps: 3m x 4n
#define EMAX    360000

// ---------------- device scratch ----------------
__device__ float g_h  [N_NODES * HDIM];
__device__ float g_xa [N_NODES * HDIM];
__device__ float g_xb [N_NODES * HDIM];
__device__ float g_dinv_g[N_NODES];
__device__ float g_dinv_r[N_NODES];
__device__ int   g_deg_g [N_NODES];
__device__ int   g_deg_r [N_NODES];
__device__ int   g_start [B_GR];
__device__ int   g_end   [B_GR];
__device__ float g_cat [B_GR * 2 * RAWF];
__device__ float g_h2  [B_GR * 512];
__device__ float g_f5  [B_GR * 5 * HDIM];
__device__ uint16_t g_wT[256 * RAWF];      // W^T fp16 [256, K]
// CSR structures (per edge set)
__device__ int   g_rowg[N_NODES + 1];
__device__ int   g_rowr[N_NODES + 1];
__device__ int   g_curg[N_NODES];
__device__ int   g_curr[N_NODES];
__device__ int   g_srcg[EMAX];
__device__ int   g_srcr[EMAX];
__device__ float g_nrmg[EMAX];
__device__ float g_nrmr[EMAX];

// ================= helpers =================
__device__ __forceinline__ uint32_t smem_u32(const void* p) {
    uint32_t a;
    asm("{ .reg .u64 t; cvta.to.shared.u64 t, %1; cvt.u32.u64 %0, t; }" : "=r"(a) : "l"(p));
    return a;
}
__device__ __forceinline__ void ldm_x4(uint32_t* r, uint32_t addr) {
    asm volatile("ldmatrix.sync.aligned.m8n8.x4.shared.b16 {%0,%1,%2,%3}, [%4];"
        : "=r"(r[0]), "=r"(r[1]), "=r"(r[2]), "=r"(r[3]) : "r"(addr));
}
__device__ __forceinline__ void mma16816(float* d, const uint32_t* a, const uint32_t* b) {
    asm volatile("mma.sync.aligned.m16n8k16.row.col.f32.f16.f16.f32 "
        "{%0,%1,%2,%3}, {%4,%5,%6,%7}, {%8,%9}, {%0,%1,%2,%3};"
        : "+f"(d[0]), "+f"(d[1]), "+f"(d[2]), "+f"(d[3])
        : "r"(a[0]), "r"(a[1]), "r"(a[2]), "r"(a[3]), "r"(b[0]), "r"(b[1]));
}
template<int N>
__device__ __forceinline__ void cp_wait() {
    asm volatile("cp.async.wait_group %0;" :: "n"(N) : "memory");
}
__device__ __forceinline__ void cp_commit() {
    asm volatile("cp.async.commit_group;" ::: "memory");
}
__device__ __forceinline__ void cp_async16(uint32_t dst, const void* src, int srcsize) {
    asm volatile("cp.async.cg.shared.global [%0], [%1], 16, %2;"
        :: "r"(dst), "l"(src), "r"(srcsize) : "memory");
}

#define MMA_SMEM (46080 + 2 * 20480)

// ======== pipelined mma.sync GEMM: H[M,256] = T(A)[M,K] @ W[K,256] ========
// T(A) = relu(A + abias) if abias != null, else A  (fused prev-layer bias+relu)
// A split hi/lo fp16, W fp16 -> 2 MMA passes.
__global__ void __launch_bounds__(NTG) gcn_gemm_mma(
    const float* __restrict__ A, const uint16_t* __restrict__ BT,
    float* __restrict__ H, const float* __restrict__ abias, int M, int K)
{
    extern __shared__ char smem[];
    const int tid  = threadIdx.x;
    const int wid  = tid >> 5;
    const int lane = tid & 31;
    const int wm   = wid >> 2;
    const int wn   = wid & 3;
    const int rowBase = blockIdx.x * BM;
    const uint32_t sb = smem_u32(smem);

    const int qa = lane >> 3, ia = lane & 7;
    const int aRowLane = ia + ((qa & 1) << 3);
    const int aKLane   = (qa >> 1) << 3;
    const int bRowLane = ia + ((qa >> 1) << 3);
    const int bKLane   = (qa & 1) << 3;

    float acc[3][8][4];
#pragma unroll
    for (int i = 0; i < 3; i++)
#pragma unroll
        for (int j = 0; j < 8; j++)
#pragma unroll
            for (int l = 0; l < 4; l++) acc[i][j][l] = 0.f;

    const int nCh = (K + 31) / 32;
    float va[2][8];

#define LDG_A(kg_) do { \
    _Pragma("unroll") \
    for (int sl = 0; sl < 2; sl++) { \
        int slot = tid + sl * NTG; \
        if (slot >= 576) break; \
        int row = slot >> 2, seg = slot & 3; \
        int grow = rowBase + row, gk = (kg_) + seg * 8; \
        _Pragma("unroll") \
        for (int j = 0; j < 8; j++) va[sl][j] = 0.f; \
        if (grow < M && gk + 8 <= K) { \
            float4 v0 = *(const float4*)(A + (size_t)grow * K + gk); \
            float4 v1 = *(const float4*)(A + (size_t)grow * K + gk + 4); \
            va[sl][0]=v0.x; va[sl][1]=v0.y; va[sl][2]=v0.z; va[sl][3]=v0.w; \
            va[sl][4]=v1.x; va[sl][5]=v1.y; va[sl][6]=v1.z; va[sl][7]=v1.w; \
        } \
    } } while (0)

#define CVT_STS_A(kg_, p_) do { \
    _Pragma("unroll") \
    for (int sl = 0; sl < 2; sl++) { \
        int slot = tid + sl * NTG; \
        if (slot >= 576) break; \
        int row = slot >> 2, seg = slot & 3; \
        int grow = rowBase + row, gk = (kg_) + seg * 8; \
        float v[8]; \
        _Pragma("unroll") \
        for (int j = 0; j < 8; j++) v[j] = va[sl][j]; \
        if (abias && grow < M && gk + 8 <= K) { \
            _Pragma("unroll") \
            for (int j = 0; j < 8; j++) v[j] = fmaxf(v[j] + abias[gk + j], 0.f); \
        } \
        uint16_t hi[8], lo[8]; \
        _Pragma("unroll") \
        for (int j = 0; j < 8; j++) { \
            __half hh = __float2half_rn(v[j]); \
            float  rs = v[j] - __half2float(hh); \
            hi[j] = __half_as_ushort(hh); \
            lo[j] = __half_as_ushort(__float2half_rn(rs)); \
        } \
        int off = (row * LDK + seg * 8) * 2; \
        *(uint4*)(smem + (p_) * 23040 + off)         = *(uint4*)hi; \
        *(uint4*)(smem + (p_) * 23040 + 11520 + off) = *(uint4*)lo; \
    } } while (0)

#define CPA_B(kg_, p_) do { \
    _Pragma("unroll") \
    for (int s = tid; s < 1024; s += NTG) { \
        int n = s >> 2, seg = s & 3; \
        int gk = (kg_) + seg * 8; \
        uint32_t dst = sb + 46080 + (p_) * 20480 + (uint32_t)(n * LDK + seg * 8) * 2; \
        cp_async16(dst, BT + (size_t)n * K + gk, (gk + 8 <= K) ? 16 : 0); \
    } } while (0)

    LDG_A(0);
    CPA_B(0, 0);
    cp_commit();
    CVT_STS_A(0, 0);

    for (int c = 0; c < nCh; c++) {
        const int p = c & 1, q = p ^ 1;
        const int kgN = (c + 1) * 32;
        __syncthreads();
        if (c + 1 < nCh) {
            LDG_A(kgN);
            CPA_B(kgN, q);
            cp_commit();
            cp_wait<1>();
        } else {
            cp_wait<0>();
        }
        __syncthreads();

        const uint32_t aHiB = sb + p * 23040;
        const uint32_t aLoB = aHiB + 11520;
        const uint32_t bB   = sb + 46080 + p * 20480;
#pragma unroll
        for (int ks = 0; ks < 2; ks++) {
            uint32_t ahi[3][4], alo[3][4];
#pragma unroll
            for (int mf = 0; mf < 3; mf++) {
                uint32_t off = (uint32_t)(((wm * 48 + mf * 16 + aRowLane) * LDK
                                          + ks * 16 + aKLane) * 2);
                ldm_x4(ahi[mf], aHiB + off);
                ldm_x4(alo[mf], aLoB + off);
            }
#pragma unroll
            for (int ng = 0; ng < 4; ng++) {
                uint32_t offB = (uint32_t)(((wn * 64 + ng * 16 + bRowLane) * LDK
                                           + ks * 16 + bKLane) * 2);
                uint32_t b[4];
                ldm_x4(b, bB + offB);
#pragma unroll
                for (int mf = 0; mf < 3; mf++) {
                    float* d0 = acc[mf][2 * ng];
                    float* d1 = acc[mf][2 * ng + 1];
                    mma16816(d0, ahi[mf], b + 0);
                    mma16816(d0, alo[mf], b + 0);
                    mma16816(d1, ahi[mf], b + 2);
                    mma16816(d1, alo[mf], b + 2);
                }
            }
        }
        if (c + 1 < nCh) CVT_STS_A(kgN, q);
    }

    // epilogue: write H only (self-loop handled by gather kernel)
#pragma unroll
    for (int mf = 0; mf < 3; mf++) {
        int rb = rowBase + wm * 48 + mf * 16 + (lane >> 2);
#pragma unroll
        for (int rr = 0; rr < 2; rr++) {
            int row = rb + rr * 8;
            if (row >= M) continue;
            float* Hp = H + (size_t)row * 256 + wn * 64 + (lane & 3) * 2;
#pragma unroll
            for (int g = 0; g < 8; g++)
                *(float2*)(Hp + g * 8) =
                    make_float2(acc[mf][g][rr * 2 + 0], acc[mf][g][rr * 2 + 1]);
        }
    }
#undef LDG_A
#undef CVT_STS_A
#undef CPA_B
}

// ---- W[K,256] -> W^T fp16 [256,K] ----
__global__ void wconv(const float* __restrict__ W, int K, uint16_t* __restrict__ wT)
{
    int idx = blockIdx.x * blockDim.x + threadIdx.x;
    if (idx >= K * 256) return;
    int k = idx >> 8, n = idx & 255;
    wT[(size_t)n * K + k] = __half_as_ushort(__float2half_rn(W[(size_t)k * 256 + n]));
}

// ---------------- graph preprocessing ----------------
__global__ void zero_f(float* p, int n) {
    for (int i = blockIdx.x * blockDim.x + threadIdx.x; i < n; i += gridDim.x * blockDim.x)
        p[i] = 0.f;
}
__global__ void zero_i(int* p, int n) {
    for (int i = blockIdx.x * blockDim.x + threadIdx.x; i < n; i += gridDim.x * blockDim.x)
        p[i] = 0;
}
__global__ void init_bounds(int* start, int* end) {
    int b = threadIdx.x;
    if (b < B_GR) { start[b] = N_NODES; end[b] = 0; }
}
__global__ void bounds_kernel(const int* __restrict__ batch, int* start, int* end, int n) {
    int i = blockIdx.x * blockDim.x + threadIdx.x;
    if (i >= n) return;
    int b = batch[i];
    atomicMin(&start[b], i);
    atomicMax(&end[b], i + 1);
}
__global__ void deg_kernel(const int* __restrict__ dst, int* deg, int E) {
    int e = blockIdx.x * blockDim.x + threadIdx.x;
    if (e < E) atomicAdd(&deg[dst[e]], 1);
}
__global__ void dinv_kernel(const int* __restrict__ deg, float* dinv, int n) {
    int i = blockIdx.x * blockDim.x + threadIdx.x;
    if (i < n) dinv[i] = rsqrtf((float)(deg[i] + 1));   // +1 self loop
}
// single-block exclusive scan: rowptr[i] = sum(deg[0..i)), also fills cursor
__global__ void scan_kernel(const int* __restrict__ deg, int* __restrict__ rowptr,
                            int* __restrict__ cursor, int n)
{
    __shared__ int buf[1024];
    __shared__ int carry;
    int tid = threadIdx.x;
    if (tid == 0) carry = 0;
    __syncthreads();
    for (int base = 0; base < n; base += 1024) {
        int i = base + tid;
        int v = (i < n) ? deg[i] : 0;
        buf[tid] = v;
        __syncthreads();
#pragma unroll
        for (int s = 1; s < 1024; s <<= 1) {
            int t = (tid >= s) ? buf[tid - s] : 0;
            __syncthreads();
            buf[tid] += t;
            __syncthreads();
        }
        if (i < n) {
            int excl = carry + buf[tid] - v;
            rowptr[i] = excl;
            cursor[i] = excl;
        }
        __syncthreads();
        if (tid == 0) carry += buf[1023];
        __syncthreads();
    }
    if (tid == 0) rowptr[n] = carry;
}
// fill CSR: src list sorted by dst, norm = dinv[s]*dinv[d]
__global__ void csr_fill(const int* __restrict__ src, const int* __restrict__ dst,
                         const float* __restrict__ dinv, int* __restrict__ cursor,
                         int* __restrict__ colsrc, float* __restrict__ norm, int E)
{
    int e = blockIdx.x * blockDim.x + threadIdx.x;
    if (e >= E) return;
    int s = src[e], d = dst[e];
    int pos = atomicAdd(&cursor[d], 1);
    colsrc[pos] = s;
    norm[pos] = dinv[s] * dinv[d];
}

// ---- CSR gather: X[d,:] = dinv[d]^2 * H[d,:] + sum_{e: dst=d} norm[e] * H[src[e],:] ----
// 64 threads per node (float4 per thread), 4 nodes per 256-thread block
__global__ void __launch_bounds__(256) gcn_gather(
    const float4* __restrict__ H4, const int* __restrict__ rowptr,
    const int* __restrict__ colsrc, const float* __restrict__ norm,
    const float* __restrict__ dinv, float4* __restrict__ X4)
{
    int node = blockIdx.x * 4 + (threadIdx.x >> 6);
    int f4 = threadIdx.x & 63;
    if (node >= N_NODES) return;
    int s0 = rowptr[node], s1 = rowptr[node + 1];
    float dv = dinv[node];
    float dv2 = dv * dv;
    float4 h = H4[(size_t)node * 64 + f4];
    float4 acc = make_float4(dv2 * h.x, dv2 * h.y, dv2 * h.z, dv2 * h.w);
    for (int j = s0; j < s1; j++) {
        float nv = norm[j];
        int s = colsrc[j];
        float4 v = H4[(size_t)s * 64 + f4];
        acc.x += nv * v.x; acc.y += nv * v.y;
        acc.z += nv * v.z; acc.w += nv * v.w;
    }
    X4[(size_t)node * 64 + f4] = acc;
}

// ---------------- fused bias+relu pooling ----------------
__global__ void pool_max_br(const float* __restrict__ x, const float* __restrict__ bias,
                            const int* __restrict__ start, const int* __restrict__ end,
                            float* __restrict__ out, int ldo)
{
    int f = threadIdx.x;
    int b = blockIdx.x;
    int s = start[b], e = end[b];
    float bv = bias[f];
    float m = -INFINITY;
    for (int r = s; r < e; r++) m = fmaxf(m, fmaxf(x[(size_t)r * HDIM + f] + bv, 0.f));
    out[(size_t)b * ldo + f] = m;
}
__global__ void pool_mean_br(const float* __restrict__ x, const float* __restrict__ bias,
                             const int* __restrict__ start, const int* __restrict__ end,
                             float* __restrict__ out, int ldo)
{
    int f = threadIdx.x;
    int b = blockIdx.x;
    int s = start[b], e = end[b];
    float bv = bias[f];
    float sum = 0.f;
    for (int r = s; r < e; r++) sum += fmaxf(x[(size_t)r * HDIM + f] + bv, 0.f);
    int cnt = e - s; if (cnt < 1) cnt = 1;
    out[(size_t)b * ldo + f] = sum / (float)cnt;
}
__global__ void pool_mean_wide(const float* __restrict__ x, int F,
                               const int* __restrict__ start, const int* __restrict__ end,
                               float* __restrict__ out, int ldo)
{
    int f = blockIdx.x * blockDim.x + threadIdx.x;
    int b = blockIdx.y;
    if (f >= F) return;
    int s = start[b], e = end[b];
    float sum = 0.f;
    for (int r = s; r < e; r++) sum += x[(size_t)r * F + f];
    int cnt = e - s; if (cnt < 1) cnt = 1;
    out[(size_t)b * ldo + f] = sum / (float)cnt;
}
__global__ void gather_root(const float* __restrict__ x, const int* __restrict__ root,
                            float* __restrict__ out, int ldo)
{
    int f = blockIdx.x * blockDim.x + threadIdx.x;
    int b = blockIdx.y;
    if (f >= RAWF) return;
    out[(size_t)b * ldo + f] = x[(size_t)root[b] * RAWF + f];
}
__global__ void prelu_bias(const float* __restrict__ in, const float* __restrict__ bias,
                           const float* __restrict__ a_ptr, float* __restrict__ out,
                           int rows, int F, int ldo)
{
    int idx = blockIdx.x * blockDim.x + threadIdx.x;
    if (idx >= rows * F) return;
    int r = idx / F, f = idx - r * F;
    float a = *a_ptr;
    float v = in[idx] + bias[f];
    out[(size_t)r * ldo + f] = v >= 0.f ? v : a * v;
}

// ---------------- FFMA GEMM (branch-2 only) ----------------
template <bool ATOMIC>
__global__ void sgemm128(const float* __restrict__ A, const float* __restrict__ B,
                         float* __restrict__ C, int M, int N, int K, int ldc, int kChunk)
{
    __shared__ float As[8][128];
    __shared__ float Bs[8][128];
    const int tid = threadIdx.x;
    const int br = blockIdx.y * 128;
    const int bc = blockIdx.x * 128;
    int k0 = blockIdx.z * kChunk;
    int k1 = k0 + kChunk; if (k1 > K) k1 = K;

    const int tRow = (tid >> 4) << 3;
    const int tCol = (tid & 15) << 3;

    float acc[8][8];
#pragma unroll
    for (int i = 0; i < 8; i++)
#pragma unroll
        for (int j = 0; j < 8; j++) acc[i][j] = 0.f;

    const int aRow = tid >> 1;
    const int aCol = (tid & 1) << 2;
    const int bRow = tid >> 5;
    const int bCol = (tid & 31) << 2;
    const int gr = br + aRow;
    const int gc = bc + bCol;

    for (int k = k0; k < k1; k += 8) {
        float4 av = make_float4(0.f, 0.f, 0.f, 0.f);
        if (gr < M) av = *(const float4*)(A + (size_t)gr * K + k + aCol);
        As[aCol + 0][aRow] = av.x;
        As[aCol + 1][aRow] = av.y;
        As[aCol + 2][aRow] = av.z;
        As[aCol + 3][aRow] = av.w;
        float4 bv = make_float4(0.f, 0.f, 0.f, 0.f);
        if (gc < N) bv = *(const float4*)(B + (size_t)(k + bRow) * N + gc);
        *(float4*)(&Bs[bRow][bCol]) = bv;
        __syncthreads();
#pragma unroll
        for (int kk = 0; kk < 8; kk++) {
            float ra[8], rb[8];
#pragma unroll
            for (int i = 0; i < 8; i++) ra[i] = As[kk][tRow + i];
#pragma unroll
            for (int j = 0; j < 8; j++) rb[j] = Bs[kk][tCol + j];
#pragma unroll
            for (int i = 0; i < 8; i++)
#pragma unroll
                for (int j = 0; j < 8; j++)
                    acc[i][j] += ra[i] * rb[j];
        }
        __syncthreads();
    }
#pragma unroll
    for (int i = 0; i < 8; i++) {
        int r = br + tRow + i;
        if (r >= M) break;
#pragma unroll
        for (int j = 0; j < 8; j++) {
            int c = bc + tCol + j;
            if (c < N) {
                if (ATOMIC) atomicAdd(&C[(size_t)r * ldc + c], acc[i][j]);
                else        C[(size_t)r * ldc + c] = acc[i][j];
            }
        }
    }
}

// ---------------- final head ----------------
__global__ void final_head(const float* __restrict__ feat, const float* __restrict__ W5,
                           const float* __restrict__ b5, float* __restrict__ out)
{
    int b = blockIdx.x;
    int t = threadIdx.x;
    float a0 = 0.f, a1 = 0.f, a2 = 0.f, a3 = 0.f;
    const float* row = feat + (size_t)b * 1280;
    for (int k = t; k < 1280; k += 128) {
        float xv = row[k];
        const float* w = W5 + (size_t)k * 4;
        a0 += xv * w[0]; a1 += xv * w[1]; a2 += xv * w[2]; a3 += xv * w[3];
    }
    __shared__ float red[128][4];
    red[t][0] = a0; red[t][1] = a1; red[t][2] = a2; red[t][3] = a3;
    __syncthreads();
    for (int sft = 64; sft > 0; sft >>= 1) {
        if (t < sft) {
#pragma unroll
            for (int c = 0; c < 4; c++) red[t][c] += red[t + sft][c];
        }
        __syncthreads();
    }
    if (t == 0) {
        float v[4];
#pragma unroll
        for (int c = 0; c < 4; c++) v[c] = red[0][c] + b5[c];
        float m = fmaxf(fmaxf(v[0], v[1]), fmaxf(v[2], v[3]));
        float sum = 0.f;
#pragma unroll
        for (int c = 0; c < 4; c++) sum += expf(v[c] - m);
        float lse = m + logf(sum);
#pragma unroll
        for (int c = 0; c < 4; c++) out[(size_t)b * 4 + c] = v[c] - lse;
    }
}

// ---------------- host orchestration ----------------
static inline void gemm_ffma(const float* A, const float* B, float* C,
                             int M, int N, int K, int ldc, int splits)
{
    dim3 grid((N + 127) / 128, (M + 127) / 128, splits);
    if (splits > 1) {
        int chunk = ((K + splits - 1) / splits + 7) & ~7;
        sgemm128<true><<<grid, 256>>>(A, B, C, M, N, K, ldc, chunk);
    } else {
        sgemm128<false><<<grid, 256>>>(A, B, C, M, N, K, ldc, K);
    }
}

extern "C" void kernel_launch(void* const* d_in, const int* in_sizes, int n_in,
                              void* d_out, int out_size)
{
    const float* graph_x = (const float*)d_in[0];
    const float* data_x  = (const float*)d_in[2];
    const int*   ei      = (const int*)d_in[3];
    const int*   rei     = (const int*)d_in[4];
    const int*   batch   = (const int*)d_in[5];
    const int*   root    = (const int*)d_in[7];
    const float* W1  = (const float*)d_in[8];
    const float* b1  = (const float*)d_in[9];
    const float* Wc0 = (const float*)d_in[10];
    const float* bc0 = (const float*)d_in[11];
    const float* Wc1 = (const float*)d_in[12];
    const float* bc1 = (const float*)d_in[13];
    const float* Wc2 = (const float*)d_in[14];
    const float* bc2 = (const float*)d_in[15];
    const float* Wl1 = (const float*)d_in[16];
    const float* bl1 = (const float*)d_in[17];
    const float* Wl2 = (const float*)d_in[18];
    const float* bl2 = (const float*)d_in[19];
    const float* pa  = (const float*)d_in[20];
    const float* W5  = (const float*)d_in[21];
    const float* b5  = (const float*)d_in[22];
    float* out = (float*)d_out;

    const int E = in_sizes[3] / 2;

    float *h, *xa, *xb, *dg, *dr, *cat, *h2, *f5, *nrmg, *nrmr;
    int *degg, *degr, *st, *en, *rowg, *rowr, *curg, *curr, *srcg, *srcr;
    uint16_t *wT;
    cudaGetSymbolAddress((void**)&h,    g_h);
    cudaGetSymbolAddress((void**)&xa,   g_xa);
    cudaGetSymbolAddress((void**)&xb,   g_xb);
    cudaGetSymbolAddress((void**)&dg,   g_dinv_g);
    cudaGetSymbolAddress((void**)&dr,   g_dinv_r);
    cudaGetSymbolAddress((void**)&degg, g_deg_g);
    cudaGetSymbolAddress((void**)&degr, g_deg_r);
    cudaGetSymbolAddress((void**)&st,   g_start);
    cudaGetSymbolAddress((void**)&en,   g_end);
    cudaGetSymbolAddress((void**)&cat,  g_cat);
    cudaGetSymbolAddress((void**)&h2,   g_h2);
    cudaGetSymbolAddress((void**)&f5,   g_f5);
    cudaGetSymbolAddress((void**)&wT,   g_wT);
    cudaGetSymbolAddress((void**)&rowg, g_rowg);
    cudaGetSymbolAddress((void**)&rowr, g_rowr);
    cudaGetSymbolAddress((void**)&curg, g_curg);
    cudaGetSymbolAddress((void**)&curr, g_curr);
    cudaGetSymbolAddress((void**)&srcg, g_srcg);
    cudaGetSymbolAddress((void**)&srcr, g_srcr);
    cudaGetSymbolAddress((void**)&nrmg, g_nrmg);
    cudaGetSymbolAddress((void**)&nrmr, g_nrmr);

    cudaFuncSetAttribute(gcn_gemm_mma, cudaFuncAttributeMaxDynamicSharedMemorySize, MMA_SMEM);

    const int NT = 256;
    const int gemmGrid = (N_NODES + BM - 1) / BM;
    const int gatherGrid = (N_NODES + 3) / 4;

    // ---- degrees + dinv + segment bounds + CSR ----
    zero_i<<<128, NT>>>(degg, N_NODES);
    zero_i<<<128, NT>>>(degr, N_NODES);
    deg_kernel<<<(E + NT - 1) / NT, NT>>>(ei + E, degg, E);
    deg_kernel<<<(E + NT - 1) / NT, NT>>>(rei + E, degr, E);
    dinv_kernel<<<(N_NODES + NT - 1) / NT, NT>>>(degg, dg, N_NODES);
    dinv_kernel<<<(N_NODES + NT - 1) / NT, NT>>>(degr, dr, N_NODES);
    init_bounds<<<1, 128>>>(st, en);
    bounds_kernel<<<(N_NODES + NT - 1) / NT, NT>>>(batch, st, en, N_NODES);
    scan_kernel<<<1, 1024>>>(degg, rowg, curg, N_NODES);
    scan_kernel<<<1, 1024>>>(degr, rowr, curr, N_NODES);
    csr_fill<<<(E + NT - 1) / NT, NT>>>(ei, ei + E, dg, curg, srcg, nrmg, E);
    csr_fill<<<(E + NT - 1) / NT, NT>>>(rei, rei + E, dr, curr, srcr, nrmr, E);

    // ---- branch 1: GCN(graph_x, W1) -> gather -> max pool (bias+relu fused) ----
    wconv<<<(FIN * 256 + NT - 1) / NT, NT>>>(W1, FIN, wT);
    gcn_gemm_mma<<<gemmGrid, NTG, MMA_SMEM>>>(graph_x, wT, h, nullptr, N_NODES, FIN);
    gcn_gather<<<gatherGrid, 256>>>((const float4*)h, rowg, srcg, nrmg, dg, (float4*)xa);
    pool_max_br<<<B_GR, HDIM>>>(xa, b1, st, en, f5 + 1024, 1280);

    // ---- branch 3: 3 GCN layers on raw graph ----
    wconv<<<(RAWF * 256 + NT - 1) / NT, NT>>>(Wc0, RAWF, wT);
    gcn_gemm_mma<<<gemmGrid, NTG, MMA_SMEM>>>(data_x, wT, h, nullptr, N_NODES, RAWF);
    gcn_gather<<<gatherGrid, 256>>>((const float4*)h, rowr, srcr, nrmr, dr, (float4*)xa);
    pool_mean_br<<<B_GR, HDIM>>>(xa, bc0, st, en, f5 + 0, 1280);

    wconv<<<(HDIM * 256 + NT - 1) / NT, NT>>>(Wc1, HDIM, wT);
    gcn_gemm_mma<<<gemmGrid, NTG, MMA_SMEM>>>(xa, wT, h, bc0, N_NODES, HDIM);
    gcn_gather<<<gatherGrid, 256>>>((const float4*)h, rowr, srcr, nrmr, dr, (float4*)xb);
    pool_mean_br<<<B_GR, HDIM>>>(xb, bc1, st, en, f5 + 256, 1280);

    wconv<<<(HDIM * 256 + NT - 1) / NT, NT>>>(Wc2, HDIM, wT);
    gcn_gemm_mma<<<gemmGrid, NTG, MMA_SMEM>>>(xb, wT, h, bc1, N_NODES, HDIM);
    gcn_gather<<<gatherGrid, 256>>>((const float4*)h, rowr, srcr, nrmr, dr, (float4*)xa);
    pool_mean_br<<<B_GR, HDIM>>>(xa, bc2, st, en, f5 + 512, 1280);

    // ---- branch 2: [segment_mean(data_x) | data_x[root]] -> MLP w/ PReLU ----
    pool_mean_wide<<<dim3((RAWF + NT - 1) / NT, B_GR), NT>>>(data_x, RAWF, st, en, cat, 2 * RAWF);
    gather_root<<<dim3((RAWF + NT - 1) / NT, B_GR), NT>>>(data_x, root, cat + RAWF, 2 * RAWF);
    zero_f<<<64, NT>>>(h2, B_GR * 512);
    gemm_ffma(cat, Wl1, h2, B_GR, 512, 2 * RAWF, 512, 25);
    prelu_bias<<<(B_GR * 512 + NT - 1) / NT, NT>>>(h2, bl1, pa, h2, B_GR, 512, 512);
    {
        float* nx = cat;
        zero_f<<<64, NT>>>(nx, B_GR * HDIM);
        gemm_ffma(h2, Wl2, nx, B_GR, HDIM, 512, HDIM, 8);
        prelu_bias<<<(B_GR * HDIM + NT - 1) / NT, NT>>>(nx, bl2, pa, f5 + 768, B_GR, HDIM, 1280);
    }

    // ---- head ----
    final_head<<<B_GR, 128>>>(f5, W5, b5, out);
}